// round 1
// baseline (speedup 1.0000x reference)
#include <cuda_runtime.h>

#define N_NODES 100000
#define N_EDGES 1600000
#define IN_CH   256
#define HID_CH  128
#define OUT_CH  64

// ---------------- scratch (device globals; no cudaMalloc allowed) ----------
__device__ float g_deg [N_NODES];
__device__ float g_dinv[N_NODES];
__device__ float g_h1[(size_t)N_NODES * HID_CH];   // x @ W1
__device__ float g_a1[(size_t)N_NODES * HID_CH];   // aggregated layer-1 (pre-relu)
__device__ float g_h2[(size_t)N_NODES * OUT_CH];   // relu(a1) @ W2
__device__ int   g_is64;

// ---------------- dtype detection (int32 vs int64 edge_index) --------------
// If int64 little-endian, every odd 32-bit word is a high word == 0 (values < 2^31).
// If int32, odd words are random edge ids in [0,100000); P(64 all zero) ~ 0.
__global__ void detect_kernel(const unsigned* __restrict__ w) {
    if (threadIdx.x == 0 && blockIdx.x == 0) {
        int is64 = 1;
        for (int i = 0; i < 64; i++)
            if (w[2 * i + 1] != 0u) { is64 = 0; break; }
        g_is64 = is64;
    }
}

__device__ __forceinline__ void load_edge(const void* ei, long long e, int is64,
                                          int& s, int& d) {
    if (is64) {
        const long long* p = (const long long*)ei;
        s = (int)p[e];
        d = (int)p[(long long)N_EDGES + e];
    } else {
        const int* p = (const int*)ei;
        s = p[e];
        d = p[(long long)N_EDGES + e];
    }
}

// ---------------- degree / normalization -----------------------------------
__global__ void init_deg_kernel() {
    int n = blockIdx.x * blockDim.x + threadIdx.x;
    if (n < N_NODES) g_deg[n] = 1.0f;   // self-loop
}

__global__ void count_deg_kernel(const void* __restrict__ ei) {
    int e = blockIdx.x * blockDim.x + threadIdx.x;
    if (e >= N_EDGES) return;
    int is64 = g_is64;
    int d;
    if (is64) d = (int)((const long long*)ei)[(long long)N_EDGES + e];
    else      d = ((const int*)ei)[(long long)N_EDGES + e];
    atomicAdd(&g_deg[d], 1.0f);
}

__global__ void dinv_kernel() {
    int n = blockIdx.x * blockDim.x + threadIdx.x;
    if (n < N_NODES) g_dinv[n] = rsqrtf(g_deg[n]);   // deg >= 1 always
}

// ---------------- fp32 tiled GEMM: out[M,NC] = act(A[M,K]) @ W[K,NC] --------
// BM=128 rows per block, full NC columns, BK=16, 8 x (NC/16) accum per thread.
template<int K, int NC, bool RELU_IN>
__global__ __launch_bounds__(256)
void gemm_kernel(const float* __restrict__ A, const float* __restrict__ W,
                 float* __restrict__ out, int M) {
    constexpr int BM = 128, BK = 16;
    constexpr int TN = NC / 16;       // 8 for NC=128, 4 for NC=64
    __shared__ float xs[BK][BM];      // k-major A tile
    __shared__ float ws[BK][NC];      // W tile (direct row copy)

    int tid  = threadIdx.x;
    int m0   = blockIdx.x * BM;
    int row0 = (tid >> 4) * 8;        // 0..120
    int col0 = (tid & 15) * TN;       // 0..NC-TN

    float acc[8][TN];
#pragma unroll
    for (int i = 0; i < 8; i++)
#pragma unroll
        for (int j = 0; j < TN; j++) acc[i][j] = 0.0f;

    for (int kk = 0; kk < K; kk += BK) {
        // A tile: 128 rows x 16 cols = 512 float4, 2 per thread
#pragma unroll
        for (int l = 0; l < 2; l++) {
            int idx = tid + l * 256;          // 0..511
            int m   = idx >> 2;               // 0..127
            int kq  = idx & 3;                // float4 within BK
            float4 v = make_float4(0.f, 0.f, 0.f, 0.f);
            int gm = m0 + m;
            if (gm < M)
                v = *(const float4*)(A + (size_t)gm * K + kk + kq * 4);
            if (RELU_IN) {
                v.x = fmaxf(v.x, 0.f); v.y = fmaxf(v.y, 0.f);
                v.z = fmaxf(v.z, 0.f); v.w = fmaxf(v.w, 0.f);
            }
            xs[kq * 4 + 0][m] = v.x;
            xs[kq * 4 + 1][m] = v.y;
            xs[kq * 4 + 2][m] = v.z;
            xs[kq * 4 + 3][m] = v.w;
        }
        // W tile: contiguous BK*NC floats starting at W[kk][0]
        constexpr int WV4 = BK * NC / 4;      // float4 count
#pragma unroll
        for (int l = 0; l < WV4 / 256; l++) {
            int idx = tid + l * 256;
            ((float4*)&ws[0][0])[idx] =
                ((const float4*)(W + (size_t)kk * NC))[idx];
        }
        __syncthreads();

#pragma unroll
        for (int k = 0; k < BK; k++) {
            float a[8], b[TN];
            *(float4*)&a[0] = *(float4*)&xs[k][row0];
            *(float4*)&a[4] = *(float4*)&xs[k][row0 + 4];
#pragma unroll
            for (int j = 0; j < TN; j += 4)
                *(float4*)&b[j] = *(float4*)&ws[k][col0 + j];
#pragma unroll
            for (int i = 0; i < 8; i++)
#pragma unroll
                for (int j = 0; j < TN; j++)
                    acc[i][j] += a[i] * b[j];
        }
        __syncthreads();
    }

#pragma unroll
    for (int i = 0; i < 8; i++) {
        int gm = m0 + row0 + i;
        if (gm < M) {
#pragma unroll
            for (int j = 0; j < TN; j += 4)
                *(float4*)(out + (size_t)gm * NC + col0 + j) = *(float4*)&acc[i][j];
        }
    }
}

// ---------------- aggregation init (bias + self-loop term) -----------------
__global__ void init_a1_kernel(const float* __restrict__ b1) {
    long long i = (long long)blockIdx.x * blockDim.x + threadIdx.x;  // float4 idx
    if (i >= (long long)N_NODES * (HID_CH / 4)) return;
    int n  = (int)(i >> 5);          // HID/4 = 32
    int cq = (int)(i & 31);
    float di = g_dinv[n];
    float w  = di * di;
    float4 h = ((const float4*)g_h1)[i];
    float4 b = ((const float4*)b1)[cq];
    float4 o;
    o.x = b.x + h.x * w; o.y = b.y + h.y * w;
    o.z = b.z + h.z * w; o.w = b.w + h.w * w;
    ((float4*)g_a1)[i] = o;
}

__global__ void init_out_kernel(const float* __restrict__ b2,
                                float* __restrict__ out) {
    long long i = (long long)blockIdx.x * blockDim.x + threadIdx.x;  // float4 idx
    if (i >= (long long)N_NODES * (OUT_CH / 4)) return;
    int n  = (int)(i >> 4);          // OUT/4 = 16
    int cq = (int)(i & 15);
    float di = g_dinv[n];
    float w  = di * di;
    float4 h = ((const float4*)g_h2)[i];
    float4 b = ((const float4*)b2)[cq];
    float4 o;
    o.x = b.x + h.x * w; o.y = b.y + h.y * w;
    o.z = b.z + h.z * w; o.w = b.w + h.w * w;
    ((float4*)out)[i] = o;
}

// ---------------- edge scatter-add: layer 1 (128 ch, 1 warp/edge) ----------
__device__ __forceinline__ void red_add_v4(float* p, float4 v) {
    asm volatile("red.global.add.v4.f32 [%0], {%1,%2,%3,%4};"
                 :: "l"(p), "f"(v.x), "f"(v.y), "f"(v.z), "f"(v.w)
                 : "memory");
}

__global__ void edge_agg1_kernel(const void* __restrict__ ei) {
    long long t = (long long)blockIdx.x * blockDim.x + threadIdx.x;
    long long e = t >> 5;
    int lane = (int)(t & 31);
    if (e >= N_EDGES) return;
    int is64 = g_is64;
    int s, d;
    load_edge(ei, e, is64, s, d);
    float w = g_dinv[s] * g_dinv[d];
    float4 v = ((const float4*)(g_h1 + (size_t)s * HID_CH))[lane];
    v.x *= w; v.y *= w; v.z *= w; v.w *= w;
    red_add_v4(g_a1 + (size_t)d * HID_CH + lane * 4, v);
}

// ---------------- edge scatter-add: layer 2 (64 ch, 16 lanes/edge) ---------
__global__ void edge_agg2_kernel(const void* __restrict__ ei,
                                 float* __restrict__ out) {
    long long t = (long long)blockIdx.x * blockDim.x + threadIdx.x;
    long long e = t >> 4;
    int sub = (int)(t & 15);
    if (e >= N_EDGES) return;
    int is64 = g_is64;
    int s, d;
    load_edge(ei, e, is64, s, d);
    float w = g_dinv[s] * g_dinv[d];
    float4 v = ((const float4*)(g_h2 + (size_t)s * OUT_CH))[sub];
    v.x *= w; v.y *= w; v.z *= w; v.w *= w;
    red_add_v4(out + (size_t)d * OUT_CH + sub * 4, v);
}

// ---------------- launch ----------------------------------------------------
extern "C" void kernel_launch(void* const* d_in, const int* in_sizes, int n_in,
                              void* d_out, int out_size) {
    const float* x  = (const float*)d_in[0];
    const void*  ei = d_in[1];
    const float* W1 = (const float*)d_in[2];
    const float* b1 = (const float*)d_in[3];
    const float* W2 = (const float*)d_in[4];
    const float* b2 = (const float*)d_in[5];
    float* out = (float*)d_out;

    float *p_h1, *p_a1, *p_h2;
    cudaGetSymbolAddress((void**)&p_h1, g_h1);
    cudaGetSymbolAddress((void**)&p_a1, g_a1);
    cudaGetSymbolAddress((void**)&p_h2, g_h2);

    detect_kernel<<<1, 32>>>((const unsigned*)ei);
    init_deg_kernel<<<(N_NODES + 255) / 256, 256>>>();
    count_deg_kernel<<<(N_EDGES + 255) / 256, 256>>>(ei);
    dinv_kernel<<<(N_NODES + 255) / 256, 256>>>();

    // layer 1: h1 = x @ W1
    gemm_kernel<IN_CH, HID_CH, false>
        <<<(N_NODES + 127) / 128, 256>>>(x, W1, p_h1, N_NODES);
    // a1 = b1 + dinv^2 * h1 (self-loop), then scatter edges
    {
        long long nt = (long long)N_NODES * (HID_CH / 4);
        init_a1_kernel<<<(unsigned)((nt + 255) / 256), 256>>>(b1);
    }
    {
        long long nt = (long long)N_EDGES * 32;
        edge_agg1_kernel<<<(unsigned)((nt + 255) / 256), 256>>>(ei);
    }

    // layer 2: h2 = relu(a1) @ W2
    gemm_kernel<HID_CH, OUT_CH, true>
        <<<(N_NODES + 127) / 128, 256>>>(p_a1, W2, p_h2, N_NODES);
    {
        long long nt = (long long)N_NODES * (OUT_CH / 4);
        init_out_kernel<<<(unsigned)((nt + 255) / 256), 256>>>(b2, out);
    }
    {
        long long nt = (long long)N_EDGES * 16;
        edge_agg2_kernel<<<(unsigned)((nt + 255) / 256), 256>>>(ei, out);
    }
}

// round 2
// speedup vs baseline: 1.5187x; 1.5187x over previous
#include <cuda_runtime.h>

#define N_NODES 100000
#define N_EDGES 1600000
#define IN_CH   256
#define HID_CH  128
#define OUT_CH  64
#define NB_SCAN ((N_NODES + 255) / 256)   // 391

// ---------------- scratch (device globals; no cudaMalloc allowed) ----------
__device__ int   g_cnt     [N_NODES];
__device__ int   g_rowstart[N_NODES];
__device__ int   g_cursor  [N_NODES];
__device__ int   g_part    [512];
__device__ int2  g_csr     [N_EDGES];           // (src, weight-as-int)
__device__ float g_dinv    [N_NODES];
__device__ float g_h1[(size_t)N_NODES * HID_CH];   // x @ W1
__device__ float g_a1[(size_t)N_NODES * HID_CH];   // aggregated layer-1 (pre-relu)
__device__ float g_h2[(size_t)N_NODES * OUT_CH];   // relu(a1) @ W2
__device__ int   g_is64;

// ---------------- dtype detection (int32 vs int64 edge_index) --------------
__global__ void detect_kernel(const unsigned* __restrict__ w) {
    if (threadIdx.x == 0 && blockIdx.x == 0) {
        int is64 = 1;
        for (int i = 0; i < 64; i++)
            if (w[2 * i + 1] != 0u) { is64 = 0; break; }
        g_is64 = is64;
    }
}

__device__ __forceinline__ void load_edge(const void* ei, long long e, int is64,
                                          int& s, int& d) {
    if (is64) {
        const long long* p = (const long long*)ei;
        s = (int)p[e];
        d = (int)p[(long long)N_EDGES + e];
    } else {
        const int* p = (const int*)ei;
        s = p[e];
        d = p[(long long)N_EDGES + e];
    }
}

// ---------------- degree histogram + normalization -------------------------
__global__ void zero_cnt_kernel() {
    int n = blockIdx.x * blockDim.x + threadIdx.x;
    if (n < N_NODES) g_cnt[n] = 0;
}

__global__ void count_deg_kernel(const void* __restrict__ ei) {
    int e = blockIdx.x * blockDim.x + threadIdx.x;
    if (e >= N_EDGES) return;
    int d;
    if (g_is64) d = (int)((const long long*)ei)[(long long)N_EDGES + e];
    else        d = ((const int*)ei)[(long long)N_EDGES + e];
    atomicAdd(&g_cnt[d], 1);
}

__global__ void dinv_kernel() {
    int n = blockIdx.x * blockDim.x + threadIdx.x;
    if (n < N_NODES) g_dinv[n] = rsqrtf((float)(g_cnt[n] + 1));  // +1 self-loop
}

// ---------------- exclusive scan over g_cnt (3 kernels) ---------------------
__global__ void scan1_kernel() {
    __shared__ int sm[256];
    int tid = threadIdx.x;
    int i = blockIdx.x * 256 + tid;
    int v = (i < N_NODES) ? g_cnt[i] : 0;
    sm[tid] = v;
    __syncthreads();
#pragma unroll
    for (int off = 1; off < 256; off <<= 1) {
        int t = (tid >= off) ? sm[tid - off] : 0;
        __syncthreads();
        sm[tid] += t;
        __syncthreads();
    }
    if (i < N_NODES) g_rowstart[i] = sm[tid] - v;   // exclusive within block
    if (tid == 255) g_part[blockIdx.x] = sm[tid];
}

__global__ void scan2_kernel() {
    __shared__ int sm[512];
    int tid = threadIdx.x;
    int v = (tid < NB_SCAN) ? g_part[tid] : 0;
    sm[tid] = v;
    __syncthreads();
#pragma unroll
    for (int off = 1; off < 512; off <<= 1) {
        int t = (tid >= off) ? sm[tid - off] : 0;
        __syncthreads();
        sm[tid] += t;
        __syncthreads();
    }
    if (tid < NB_SCAN) g_part[tid] = sm[tid] - v;   // exclusive
}

__global__ void scan3_kernel() {
    int i = blockIdx.x * 256 + threadIdx.x;
    if (i < N_NODES) {
        int r = g_rowstart[i] + g_part[blockIdx.x];
        g_rowstart[i] = r;
        g_cursor[i] = r;
    }
}

// ---------------- CSR fill ---------------------------------------------------
__global__ void fill_csr_kernel(const void* __restrict__ ei) {
    int e = blockIdx.x * blockDim.x + threadIdx.x;
    if (e >= N_EDGES) return;
    int s, d;
    load_edge(ei, e, g_is64, s, d);
    float w = g_dinv[s] * g_dinv[d];
    int slot = atomicAdd(&g_cursor[d], 1);
    g_csr[slot] = make_int2(s, __float_as_int(w));
}

// ---------------- fp32 tiled GEMM: out[M,NC] = act(A[M,K]) @ W[K,NC] --------
template<int K, int NC, bool RELU_IN>
__global__ __launch_bounds__(256)
void gemm_kernel(const float* __restrict__ A, const float* __restrict__ W,
                 float* __restrict__ out, int M) {
    constexpr int BM = 128, BK = 16;
    constexpr int TN = NC / 16;       // 8 for NC=128, 4 for NC=64
    __shared__ float xs[BK][BM];      // k-major A tile
    __shared__ float ws[BK][NC];      // W tile

    int tid  = threadIdx.x;
    int m0   = blockIdx.x * BM;
    int row0 = (tid >> 4) * 8;
    int col0 = (tid & 15) * TN;

    float acc[8][TN];
#pragma unroll
    for (int i = 0; i < 8; i++)
#pragma unroll
        for (int j = 0; j < TN; j++) acc[i][j] = 0.0f;

    for (int kk = 0; kk < K; kk += BK) {
#pragma unroll
        for (int l = 0; l < 2; l++) {
            int idx = tid + l * 256;
            int m   = idx >> 2;
            int kq  = idx & 3;
            float4 v = make_float4(0.f, 0.f, 0.f, 0.f);
            int gm = m0 + m;
            if (gm < M)
                v = *(const float4*)(A + (size_t)gm * K + kk + kq * 4);
            if (RELU_IN) {
                v.x = fmaxf(v.x, 0.f); v.y = fmaxf(v.y, 0.f);
                v.z = fmaxf(v.z, 0.f); v.w = fmaxf(v.w, 0.f);
            }
            xs[kq * 4 + 0][m] = v.x;
            xs[kq * 4 + 1][m] = v.y;
            xs[kq * 4 + 2][m] = v.z;
            xs[kq * 4 + 3][m] = v.w;
        }
        constexpr int WV4 = BK * NC / 4;
#pragma unroll
        for (int l = 0; l < WV4 / 256; l++) {
            int idx = tid + l * 256;
            ((float4*)&ws[0][0])[idx] =
                ((const float4*)(W + (size_t)kk * NC))[idx];
        }
        __syncthreads();

#pragma unroll
        for (int k = 0; k < BK; k++) {
            float a[8], b[TN];
            *(float4*)&a[0] = *(float4*)&xs[k][row0];
            *(float4*)&a[4] = *(float4*)&xs[k][row0 + 4];
#pragma unroll
            for (int j = 0; j < TN; j += 4)
                *(float4*)&b[j] = *(float4*)&ws[k][col0 + j];
#pragma unroll
            for (int i = 0; i < 8; i++)
#pragma unroll
                for (int j = 0; j < TN; j++)
                    acc[i][j] += a[i] * b[j];
        }
        __syncthreads();
    }

#pragma unroll
    for (int i = 0; i < 8; i++) {
        int gm = m0 + row0 + i;
        if (gm < M) {
#pragma unroll
            for (int j = 0; j < TN; j += 4)
                *(float4*)(out + (size_t)gm * NC + col0 + j) = *(float4*)&acc[i][j];
        }
    }
}

// ---------------- CSR aggregation: layer 1 (warp per node, float4/lane) -----
__global__ __launch_bounds__(256)
void agg1_kernel(const float* __restrict__ b1) {
    int warp = (blockIdx.x * blockDim.x + threadIdx.x) >> 5;
    int lane = threadIdx.x & 31;
    if (warp >= N_NODES) return;
    int beg = g_rowstart[warp];
    int cnt = g_cnt[warp];

    float4 acc = make_float4(0.f, 0.f, 0.f, 0.f);
    int j = 0;
    for (; j + 1 < cnt; j += 2) {
        int2 e0 = __ldg(&g_csr[beg + j]);
        int2 e1 = __ldg(&g_csr[beg + j + 1]);
        float w0 = __int_as_float(e0.y);
        float w1 = __int_as_float(e1.y);
        float4 v0 = __ldg((const float4*)(g_h1 + (size_t)e0.x * HID_CH) + lane);
        float4 v1 = __ldg((const float4*)(g_h1 + (size_t)e1.x * HID_CH) + lane);
        acc.x += w0 * v0.x + w1 * v1.x;
        acc.y += w0 * v0.y + w1 * v1.y;
        acc.z += w0 * v0.z + w1 * v1.z;
        acc.w += w0 * v0.w + w1 * v1.w;
    }
    if (j < cnt) {
        int2 e = __ldg(&g_csr[beg + j]);
        float w = __int_as_float(e.y);
        float4 v = __ldg((const float4*)(g_h1 + (size_t)e.x * HID_CH) + lane);
        acc.x += w * v.x; acc.y += w * v.y;
        acc.z += w * v.z; acc.w += w * v.w;
    }
    // self-loop + bias
    float di = g_dinv[warp];
    float sw = di * di;
    float4 h = ((const float4*)(g_h1 + (size_t)warp * HID_CH))[lane];
    float4 b = ((const float4*)b1)[lane];
    acc.x += b.x + sw * h.x;
    acc.y += b.y + sw * h.y;
    acc.z += b.z + sw * h.z;
    acc.w += b.w + sw * h.w;
    ((float4*)(g_a1 + (size_t)warp * HID_CH))[lane] = acc;
}

// ---------------- CSR aggregation: layer 2 (16 lanes per node, float4) ------
__global__ __launch_bounds__(256)
void agg2_kernel(const float* __restrict__ b2, float* __restrict__ out) {
    int grp  = (blockIdx.x * blockDim.x + threadIdx.x) >> 4;
    int lane = threadIdx.x & 15;
    if (grp >= N_NODES) return;
    int beg = g_rowstart[grp];
    int cnt = g_cnt[grp];

    float4 acc = make_float4(0.f, 0.f, 0.f, 0.f);
    int j = 0;
    for (; j + 1 < cnt; j += 2) {
        int2 e0 = __ldg(&g_csr[beg + j]);
        int2 e1 = __ldg(&g_csr[beg + j + 1]);
        float w0 = __int_as_float(e0.y);
        float w1 = __int_as_float(e1.y);
        float4 v0 = __ldg((const float4*)(g_h2 + (size_t)e0.x * OUT_CH) + lane);
        float4 v1 = __ldg((const float4*)(g_h2 + (size_t)e1.x * OUT_CH) + lane);
        acc.x += w0 * v0.x + w1 * v1.x;
        acc.y += w0 * v0.y + w1 * v1.y;
        acc.z += w0 * v0.z + w1 * v1.z;
        acc.w += w0 * v0.w + w1 * v1.w;
    }
    if (j < cnt) {
        int2 e = __ldg(&g_csr[beg + j]);
        float w = __int_as_float(e.y);
        float4 v = __ldg((const float4*)(g_h2 + (size_t)e.x * OUT_CH) + lane);
        acc.x += w * v.x; acc.y += w * v.y;
        acc.z += w * v.z; acc.w += w * v.w;
    }
    float di = g_dinv[grp];
    float sw = di * di;
    float4 h = ((const float4*)(g_h2 + (size_t)grp * OUT_CH))[lane];
    float4 b = ((const float4*)b2)[lane];
    acc.x += b.x + sw * h.x;
    acc.y += b.y + sw * h.y;
    acc.z += b.z + sw * h.z;
    acc.w += b.w + sw * h.w;
    ((float4*)(out + (size_t)grp * OUT_CH))[lane] = acc;
}

// ---------------- launch ----------------------------------------------------
extern "C" void kernel_launch(void* const* d_in, const int* in_sizes, int n_in,
                              void* d_out, int out_size) {
    const float* x  = (const float*)d_in[0];
    const void*  ei = d_in[1];
    const float* W1 = (const float*)d_in[2];
    const float* b1 = (const float*)d_in[3];
    const float* W2 = (const float*)d_in[4];
    const float* b2 = (const float*)d_in[5];
    float* out = (float*)d_out;

    float *p_h1, *p_a1, *p_h2;
    cudaGetSymbolAddress((void**)&p_h1, g_h1);
    cudaGetSymbolAddress((void**)&p_a1, g_a1);
    cudaGetSymbolAddress((void**)&p_h2, g_h2);

    detect_kernel<<<1, 32>>>((const unsigned*)ei);

    // degree histogram + dinv + CSR build
    zero_cnt_kernel<<<NB_SCAN, 256>>>();
    count_deg_kernel<<<(N_EDGES + 255) / 256, 256>>>(ei);
    dinv_kernel<<<NB_SCAN, 256>>>();
    scan1_kernel<<<NB_SCAN, 256>>>();
    scan2_kernel<<<1, 512>>>();
    scan3_kernel<<<NB_SCAN, 256>>>();
    fill_csr_kernel<<<(N_EDGES + 255) / 256, 256>>>(ei);

    // layer 1: h1 = x @ W1 ; a1 = bias + norm-agg(h1)
    gemm_kernel<IN_CH, HID_CH, false>
        <<<(N_NODES + 127) / 128, 256>>>(x, W1, p_h1, N_NODES);
    agg1_kernel<<<(N_NODES * 32 + 255) / 256, 256>>>(b1);

    // layer 2: h2 = relu(a1) @ W2 ; out = bias + norm-agg(h2)
    gemm_kernel<HID_CH, OUT_CH, true>
        <<<(N_NODES + 127) / 128, 256>>>(p_a1, W2, p_h2, N_NODES);
    agg2_kernel<<<(N_NODES * 16 + 255) / 256, 256>>>(b2, out);
}

// round 3
// speedup vs baseline: 2.0619x; 1.3576x over previous
#include <cuda_runtime.h>

#define N_NODES 100000
#define N_EDGES 1600000
#define IN_CH   256
#define HID_CH  128
#define OUT_CH  64
#define NB_SCAN ((N_NODES + 255) / 256)   // 391

// ---------------- scratch (device globals; no cudaMalloc allowed) ----------
__device__ int   g_cnt     [N_NODES];
__device__ int   g_rowstart[N_NODES];
__device__ int   g_cursor  [N_NODES];
__device__ int   g_part    [512];
__device__ int2  g_csr     [N_EDGES];           // (src, weight-as-int)
__device__ float g_dinv    [N_NODES];
__device__ float g_h1[(size_t)N_NODES * HID_CH];   // x @ W1
__device__ float g_a1[(size_t)N_NODES * HID_CH];   // aggregated layer-1 (pre-relu)
__device__ float g_h2[(size_t)N_NODES * OUT_CH];   // relu(a1) @ W2
__device__ int   g_is64;

// ---------------- dtype detection (int32 vs int64 edge_index) --------------
__global__ void detect_kernel(const unsigned* __restrict__ w) {
    if (threadIdx.x == 0 && blockIdx.x == 0) {
        int is64 = 1;
        for (int i = 0; i < 64; i++)
            if (w[2 * i + 1] != 0u) { is64 = 0; break; }
        g_is64 = is64;
    }
}

__device__ __forceinline__ void load_edge(const void* ei, long long e, int is64,
                                          int& s, int& d) {
    if (is64) {
        const long long* p = (const long long*)ei;
        s = (int)p[e];
        d = (int)p[(long long)N_EDGES + e];
    } else {
        const int* p = (const int*)ei;
        s = p[e];
        d = p[(long long)N_EDGES + e];
    }
}

// ---------------- degree histogram + normalization -------------------------
__global__ void zero_cnt_kernel() {
    int n = blockIdx.x * blockDim.x + threadIdx.x;
    if (n < N_NODES) g_cnt[n] = 0;
}

__global__ void count_deg_kernel(const void* __restrict__ ei) {
    int e = blockIdx.x * blockDim.x + threadIdx.x;
    if (e >= N_EDGES) return;
    int d;
    if (g_is64) d = (int)((const long long*)ei)[(long long)N_EDGES + e];
    else        d = ((const int*)ei)[(long long)N_EDGES + e];
    atomicAdd(&g_cnt[d], 1);
}

__global__ void dinv_kernel() {
    int n = blockIdx.x * blockDim.x + threadIdx.x;
    if (n < N_NODES) g_dinv[n] = rsqrtf((float)(g_cnt[n] + 1));  // +1 self-loop
}

// ---------------- exclusive scan over g_cnt (3 kernels) ---------------------
__global__ void scan1_kernel() {
    __shared__ int sm[256];
    int tid = threadIdx.x;
    int i = blockIdx.x * 256 + tid;
    int v = (i < N_NODES) ? g_cnt[i] : 0;
    sm[tid] = v;
    __syncthreads();
#pragma unroll
    for (int off = 1; off < 256; off <<= 1) {
        int t = (tid >= off) ? sm[tid - off] : 0;
        __syncthreads();
        sm[tid] += t;
        __syncthreads();
    }
    if (i < N_NODES) g_rowstart[i] = sm[tid] - v;
    if (tid == 255) g_part[blockIdx.x] = sm[tid];
}

__global__ void scan2_kernel() {
    __shared__ int sm[512];
    int tid = threadIdx.x;
    int v = (tid < NB_SCAN) ? g_part[tid] : 0;
    sm[tid] = v;
    __syncthreads();
#pragma unroll
    for (int off = 1; off < 512; off <<= 1) {
        int t = (tid >= off) ? sm[tid - off] : 0;
        __syncthreads();
        sm[tid] += t;
        __syncthreads();
    }
    if (tid < NB_SCAN) g_part[tid] = sm[tid] - v;
}

__global__ void scan3_kernel() {
    int i = blockIdx.x * 256 + threadIdx.x;
    if (i < N_NODES) {
        int r = g_rowstart[i] + g_part[blockIdx.x];
        g_rowstart[i] = r;
        g_cursor[i] = r;
    }
}

// ---------------- CSR fill ---------------------------------------------------
__global__ void fill_csr_kernel(const void* __restrict__ ei) {
    int e = blockIdx.x * blockDim.x + threadIdx.x;
    if (e >= N_EDGES) return;
    int s, d;
    load_edge(ei, e, g_is64, s, d);
    float w = g_dinv[s] * g_dinv[d];
    int slot = atomicAdd(&g_cursor[d], 1);
    g_csr[slot] = make_int2(s, __float_as_int(w));
}

// ---------------- bf16 hi/lo split helpers ----------------------------------
__device__ __forceinline__ void split_bf16(float x, unsigned& h, unsigned& l) {
    unsigned xb = __float_as_uint(x);
    unsigned hr = (xb + 0x7FFFu + ((xb >> 16) & 1u)) >> 16;   // RN-even bf16
    float hf = __uint_as_float(hr << 16);
    float lf = x - hf;
    unsigned lb = __float_as_uint(lf);
    unsigned lr = (lb + 0x7FFFu + ((lb >> 16) & 1u)) >> 16;
    h = hr; l = lr;
}

__device__ __forceinline__ void mma_bf16(float* c, const unsigned* a,
                                         unsigned b0, unsigned b1) {
    asm volatile(
        "mma.sync.aligned.m16n8k16.row.col.f32.bf16.bf16.f32 "
        "{%0,%1,%2,%3},{%4,%5,%6,%7},{%8,%9},{%0,%1,%2,%3};"
        : "+f"(c[0]), "+f"(c[1]), "+f"(c[2]), "+f"(c[3])
        : "r"(a[0]), "r"(a[1]), "r"(a[2]), "r"(a[3]), "r"(b0), "r"(b1));
}

// ---------------- tensor-core GEMM (bf16x3 fp32 emulation) ------------------
// out[M,NC] = act(A[M,K]) @ W[K,NC]; block = 128 rows x NC cols, 8 warps.
// smem tiles: A 128xBK32, W BK32xNC, each as hi+lo bf16 packed 2-per-word,
// row stride 20 words (16 data + 4 pad) -> conflict-free fragment loads.
template<int K, int NC, bool RELU_IN>
__global__ __launch_bounds__(256)
void mma_gemm_kernel(const float* __restrict__ A, const float* __restrict__ W,
                     float* __restrict__ out, int M) {
    constexpr int BK = 32;
    constexpr int STRIDE = 20;                 // words per row
    constexpr int WARPS_N = (NC == 128) ? 2 : 1;
    constexpr int WARPS_M = 8 / WARPS_N;       // 4 or 8
    constexpr int MT = 128 / (WARPS_M * 16);   // m16-tiles per warp: 2 or 1
    constexpr int ITB = (16 * NC) / 256;       // W items per thread per chunk

    __shared__ unsigned Ah[128 * STRIDE], Al[128 * STRIDE];
    __shared__ unsigned Bh[NC * STRIDE],  Bl[NC * STRIDE];

    int tid = threadIdx.x, wid = tid >> 5, lane = tid & 31;
    int g = lane >> 2, t4 = lane & 3;
    int warp_m = (wid % WARPS_M) * (MT * 16);
    int warp_n = (wid / WARPS_M) * 64;
    int m0 = blockIdx.x * 128;

    float acc[MT][8][4];
#pragma unroll
    for (int mt = 0; mt < MT; mt++)
#pragma unroll
        for (int nt = 0; nt < 8; nt++)
#pragma unroll
            for (int i = 0; i < 4; i++) acc[mt][nt][i] = 0.0f;

    for (int kk = 0; kk < K; kk += BK) {
        // ---- A tile: 128 rows x 32 cols, 1024 float4, 4 per thread ----
#pragma unroll
        for (int i = 0; i < 4; i++) {
            int idx = i * 256 + tid;
            int r = idx >> 3, c4 = idx & 7;
            int gm = m0 + r;
            float4 v = make_float4(0.f, 0.f, 0.f, 0.f);
            if (gm < M)
                v = *(const float4*)(A + (size_t)gm * K + kk + c4 * 4);
            if (RELU_IN) {
                v.x = fmaxf(v.x, 0.f); v.y = fmaxf(v.y, 0.f);
                v.z = fmaxf(v.z, 0.f); v.w = fmaxf(v.w, 0.f);
            }
            unsigned hx, lx, hy, ly, hz, lz, hw, lw;
            split_bf16(v.x, hx, lx); split_bf16(v.y, hy, ly);
            split_bf16(v.z, hz, lz); split_bf16(v.w, hw, lw);
            int base = r * STRIDE + c4 * 2;
            *(uint2*)&Ah[base] = make_uint2((hy << 16) | hx, (hw << 16) | hz);
            *(uint2*)&Al[base] = make_uint2((ly << 16) | lx, (lw << 16) | lz);
        }
        // ---- W tile: 32 x NC, packed 2 k per word, column-major-ish ----
#pragma unroll
        for (int i = 0; i < ITB; i++) {
            int idx = i * 256 + tid;
            int n = idx & (NC - 1), k2 = idx >> ((NC == 128) ? 7 : 6);
            const float* wp = W + (size_t)(kk + k2 * 2) * NC + n;
            float w0 = wp[0], w1 = wp[NC];
            unsigned h0, l0, h1, l1;
            split_bf16(w0, h0, l0); split_bf16(w1, h1, l1);
            Bh[n * STRIDE + k2] = (h1 << 16) | h0;
            Bl[n * STRIDE + k2] = (l1 << 16) | l0;
        }
        __syncthreads();

#pragma unroll
        for (int ks = 0; ks < 2; ks++) {
            unsigned ah[MT][4], al[MT][4];
#pragma unroll
            for (int mt = 0; mt < MT; mt++) {
                int r0 = (warp_m + mt * 16 + g) * STRIDE + ks * 8 + t4;
                int r1 = (warp_m + mt * 16 + g + 8) * STRIDE + ks * 8 + t4;
                ah[mt][0] = Ah[r0];     ah[mt][1] = Ah[r1];
                ah[mt][2] = Ah[r0 + 4]; ah[mt][3] = Ah[r1 + 4];
                al[mt][0] = Al[r0];     al[mt][1] = Al[r1];
                al[mt][2] = Al[r0 + 4]; al[mt][3] = Al[r1 + 4];
            }
#pragma unroll
            for (int nt = 0; nt < 8; nt++) {
                int bi = (warp_n + nt * 8 + g) * STRIDE + ks * 8 + t4;
                unsigned bh0 = Bh[bi], bh1 = Bh[bi + 4];
                unsigned bl0 = Bl[bi], bl1 = Bl[bi + 4];
#pragma unroll
                for (int mt = 0; mt < MT; mt++) {
                    mma_bf16(acc[mt][nt], ah[mt], bh0, bh1);  // hi*hi
                    mma_bf16(acc[mt][nt], ah[mt], bl0, bl1);  // hi*lo
                    mma_bf16(acc[mt][nt], al[mt], bh0, bh1);  // lo*hi
                }
            }
        }
        __syncthreads();
    }

    // ---- epilogue ----
#pragma unroll
    for (int mt = 0; mt < MT; mt++) {
        int r0 = m0 + warp_m + mt * 16 + g;
        int r1 = r0 + 8;
#pragma unroll
        for (int nt = 0; nt < 8; nt++) {
            int col = warp_n + nt * 8 + t4 * 2;
            if (r0 < M)
                *(float2*)(out + (size_t)r0 * NC + col) =
                    make_float2(acc[mt][nt][0], acc[mt][nt][1]);
            if (r1 < M)
                *(float2*)(out + (size_t)r1 * NC + col) =
                    make_float2(acc[mt][nt][2], acc[mt][nt][3]);
        }
    }
}

// ---------------- CSR aggregation: layer 1 (warp per node, float4/lane) -----
__global__ __launch_bounds__(256)
void agg1_kernel(const float* __restrict__ b1) {
    int warp = (blockIdx.x * blockDim.x + threadIdx.x) >> 5;
    int lane = threadIdx.x & 31;
    if (warp >= N_NODES) return;
    int beg = g_rowstart[warp];
    int cnt = g_cnt[warp];

    float4 acc = make_float4(0.f, 0.f, 0.f, 0.f);
    int j = 0;
    for (; j + 1 < cnt; j += 2) {
        int2 e0 = __ldg(&g_csr[beg + j]);
        int2 e1 = __ldg(&g_csr[beg + j + 1]);
        float w0 = __int_as_float(e0.y);
        float w1 = __int_as_float(e1.y);
        float4 v0 = __ldg((const float4*)(g_h1 + (size_t)e0.x * HID_CH) + lane);
        float4 v1 = __ldg((const float4*)(g_h1 + (size_t)e1.x * HID_CH) + lane);
        acc.x += w0 * v0.x + w1 * v1.x;
        acc.y += w0 * v0.y + w1 * v1.y;
        acc.z += w0 * v0.z + w1 * v1.z;
        acc.w += w0 * v0.w + w1 * v1.w;
    }
    if (j < cnt) {
        int2 e = __ldg(&g_csr[beg + j]);
        float w = __int_as_float(e.y);
        float4 v = __ldg((const float4*)(g_h1 + (size_t)e.x * HID_CH) + lane);
        acc.x += w * v.x; acc.y += w * v.y;
        acc.z += w * v.z; acc.w += w * v.w;
    }
    float di = g_dinv[warp];
    float sw = di * di;
    float4 h = ((const float4*)(g_h1 + (size_t)warp * HID_CH))[lane];
    float4 b = ((const float4*)b1)[lane];
    acc.x += b.x + sw * h.x;
    acc.y += b.y + sw * h.y;
    acc.z += b.z + sw * h.z;
    acc.w += b.w + sw * h.w;
    ((float4*)(g_a1 + (size_t)warp * HID_CH))[lane] = acc;
}

// ---------------- CSR aggregation: layer 2 (16 lanes per node, float4) ------
__global__ __launch_bounds__(256)
void agg2_kernel(const float* __restrict__ b2, float* __restrict__ out) {
    int grp  = (blockIdx.x * blockDim.x + threadIdx.x) >> 4;
    int lane = threadIdx.x & 15;
    if (grp >= N_NODES) return;
    int beg = g_rowstart[grp];
    int cnt = g_cnt[grp];

    float4 acc = make_float4(0.f, 0.f, 0.f, 0.f);
    int j = 0;
    for (; j + 1 < cnt; j += 2) {
        int2 e0 = __ldg(&g_csr[beg + j]);
        int2 e1 = __ldg(&g_csr[beg + j + 1]);
        float w0 = __int_as_float(e0.y);
        float w1 = __int_as_float(e1.y);
        float4 v0 = __ldg((const float4*)(g_h2 + (size_t)e0.x * OUT_CH) + lane);
        float4 v1 = __ldg((const float4*)(g_h2 + (size_t)e1.x * OUT_CH) + lane);
        acc.x += w0 * v0.x + w1 * v1.x;
        acc.y += w0 * v0.y + w1 * v1.y;
        acc.z += w0 * v0.z + w1 * v1.z;
        acc.w += w0 * v0.w + w1 * v1.w;
    }
    if (j < cnt) {
        int2 e = __ldg(&g_csr[beg + j]);
        float w = __int_as_float(e.y);
        float4 v = __ldg((const float4*)(g_h2 + (size_t)e.x * OUT_CH) + lane);
        acc.x += w * v.x; acc.y += w * v.y;
        acc.z += w * v.z; acc.w += w * v.w;
    }
    float di = g_dinv[grp];
    float sw = di * di;
    float4 h = ((const float4*)(g_h2 + (size_t)grp * OUT_CH))[lane];
    float4 b = ((const float4*)b2)[lane];
    acc.x += b.x + sw * h.x;
    acc.y += b.y + sw * h.y;
    acc.z += b.z + sw * h.z;
    acc.w += b.w + sw * h.w;
    ((float4*)(out + (size_t)grp * OUT_CH))[lane] = acc;
}

// ---------------- launch ----------------------------------------------------
extern "C" void kernel_launch(void* const* d_in, const int* in_sizes, int n_in,
                              void* d_out, int out_size) {
    const float* x  = (const float*)d_in[0];
    const void*  ei = d_in[1];
    const float* W1 = (const float*)d_in[2];
    const float* b1 = (const float*)d_in[3];
    const float* W2 = (const float*)d_in[4];
    const float* b2 = (const float*)d_in[5];
    float* out = (float*)d_out;

    float *p_h1, *p_a1, *p_h2;
    cudaGetSymbolAddress((void**)&p_h1, g_h1);
    cudaGetSymbolAddress((void**)&p_a1, g_a1);
    cudaGetSymbolAddress((void**)&p_h2, g_h2);

    detect_kernel<<<1, 32>>>((const unsigned*)ei);

    // degree histogram + dinv + CSR build
    zero_cnt_kernel<<<NB_SCAN, 256>>>();
    count_deg_kernel<<<(N_EDGES + 255) / 256, 256>>>(ei);
    dinv_kernel<<<NB_SCAN, 256>>>();
    scan1_kernel<<<NB_SCAN, 256>>>();
    scan2_kernel<<<1, 512>>>();
    scan3_kernel<<<NB_SCAN, 256>>>();
    fill_csr_kernel<<<(N_EDGES + 255) / 256, 256>>>(ei);

    // layer 1: h1 = x @ W1 ; a1 = bias + norm-agg(h1)
    mma_gemm_kernel<IN_CH, HID_CH, false>
        <<<(N_NODES + 127) / 128, 256>>>(x, W1, p_h1, N_NODES);
    agg1_kernel<<<(N_NODES * 32 + 255) / 256, 256>>>(b1);

    // layer 2: h2 = relu(a1) @ W2 ; out = bias + norm-agg(h2)
    mma_gemm_kernel<HID_CH, OUT_CH, true>
        <<<(N_NODES + 127) / 128, 256>>>(p_a1, W2, p_h2, N_NODES);
    agg2_kernel<<<(N_NODES * 16 + 255) / 256, 256>>>(b2, out);
}

// round 4
// speedup vs baseline: 2.1328x; 1.0344x over previous
#include <cuda_runtime.h>
#include <cuda_fp16.h>

#define N_NODES 100000
#define N_EDGES 1600000
#define IN_CH   256
#define HID_CH  128
#define OUT_CH  64
#define NB_SCAN ((N_NODES + 255) / 256)   // 391

// ---------------- scratch (device globals; no cudaMalloc allowed) ----------
__device__ int      g_cnt     [N_NODES];
__device__ int      g_rowstart[N_NODES];
__device__ int      g_cursor  [N_NODES];
__device__ int      g_part    [512];
__device__ int2     g_csr     [N_EDGES];          // (src, weight-as-int)
__device__ float    g_dinv    [N_NODES];
__device__ __half   g_h1h[(size_t)N_NODES * HID_CH];   // x @ W1   (fp16)
__device__ float    g_a1 [(size_t)N_NODES * HID_CH];   // aggregated layer-1
__device__ __half   g_h2h[(size_t)N_NODES * OUT_CH];   // relu(a1) @ W2 (fp16)
__device__ unsigned g_W1h[(IN_CH / 2) * HID_CH];   // pre-split bf16 hi packed
__device__ unsigned g_W1l[(IN_CH / 2) * HID_CH];
__device__ unsigned g_W2h[(HID_CH / 2) * OUT_CH];
__device__ unsigned g_W2l[(HID_CH / 2) * OUT_CH];
__device__ int      g_is64;

// ---------------- bf16 hi/lo split ------------------------------------------
__device__ __forceinline__ void split_bf16(float x, unsigned& h, unsigned& l) {
    unsigned xb = __float_as_uint(x);
    unsigned hr = (xb + 0x7FFFu + ((xb >> 16) & 1u)) >> 16;   // RN-even bf16
    float hf = __uint_as_float(hr << 16);
    float lf = x - hf;
    unsigned lb = __float_as_uint(lf);
    unsigned lr = (lb + 0x7FFFu + ((lb >> 16) & 1u)) >> 16;
    h = hr; l = lr;
}

// ---------------- prep: zero counters + dtype detect ------------------------
__global__ void zero_detect_kernel(const unsigned* __restrict__ w) {
    int n = blockIdx.x * blockDim.x + threadIdx.x;
    if (n < N_NODES) g_cnt[n] = 0;
    if (n == 0) {
        int is64 = 1;
        for (int i = 0; i < 64; i++)
            if (w[2 * i + 1] != 0u) { is64 = 0; break; }
        g_is64 = is64;
    }
}

__device__ __forceinline__ void load_edge(const void* ei, long long e, int is64,
                                          int& s, int& d) {
    if (is64) {
        const long long* p = (const long long*)ei;
        s = (int)p[e];
        d = (int)p[(long long)N_EDGES + e];
    } else {
        const int* p = (const int*)ei;
        s = p[e];
        d = p[(long long)N_EDGES + e];
    }
}

__global__ void count_deg_kernel(const void* __restrict__ ei) {
    int e = blockIdx.x * blockDim.x + threadIdx.x;
    if (e >= N_EDGES) return;
    int d;
    if (g_is64) d = (int)((const long long*)ei)[(long long)N_EDGES + e];
    else        d = ((const int*)ei)[(long long)N_EDGES + e];
    atomicAdd(&g_cnt[d], 1);
}

// ---------------- W pre-split (bf16 hi/lo, packed 2-k-per-word) -------------
__global__ void wsplit_kernel(const float* __restrict__ W1,
                              const float* __restrict__ W2) {
    int i = blockIdx.x * blockDim.x + threadIdx.x;
    if (i < (IN_CH / 2) * HID_CH) {
        int k2 = i / HID_CH, n = i % HID_CH;
        float w0 = W1[(size_t)(2 * k2) * HID_CH + n];
        float w1 = W1[(size_t)(2 * k2 + 1) * HID_CH + n];
        unsigned h0, l0, h1, l1;
        split_bf16(w0, h0, l0); split_bf16(w1, h1, l1);
        g_W1h[i] = (h1 << 16) | h0;
        g_W1l[i] = (l1 << 16) | l0;
    }
    if (i < (HID_CH / 2) * OUT_CH) {
        int k2 = i / OUT_CH, n = i % OUT_CH;
        float w0 = W2[(size_t)(2 * k2) * OUT_CH + n];
        float w1 = W2[(size_t)(2 * k2 + 1) * OUT_CH + n];
        unsigned h0, l0, h1, l1;
        split_bf16(w0, h0, l0); split_bf16(w1, h1, l1);
        g_W2h[i] = (h1 << 16) | h0;
        g_W2l[i] = (l1 << 16) | l0;
    }
}

// ---------------- scans (dinv fused into scan1) ------------------------------
__global__ void scan1_kernel() {
    __shared__ int sm[256];
    int tid = threadIdx.x;
    int i = blockIdx.x * 256 + tid;
    int v = (i < N_NODES) ? g_cnt[i] : 0;
    if (i < N_NODES) g_dinv[i] = rsqrtf((float)(v + 1));   // +1 self-loop
    sm[tid] = v;
    __syncthreads();
#pragma unroll
    for (int off = 1; off < 256; off <<= 1) {
        int t = (tid >= off) ? sm[tid - off] : 0;
        __syncthreads();
        sm[tid] += t;
        __syncthreads();
    }
    if (i < N_NODES) g_rowstart[i] = sm[tid] - v;
    if (tid == 255) g_part[blockIdx.x] = sm[tid];
}

__global__ void scan2_kernel() {
    __shared__ int sm[512];
    int tid = threadIdx.x;
    int v = (tid < NB_SCAN) ? g_part[tid] : 0;
    sm[tid] = v;
    __syncthreads();
#pragma unroll
    for (int off = 1; off < 512; off <<= 1) {
        int t = (tid >= off) ? sm[tid - off] : 0;
        __syncthreads();
        sm[tid] += t;
        __syncthreads();
    }
    if (tid < NB_SCAN) g_part[tid] = sm[tid] - v;
}

__global__ void scan3_kernel() {
    int i = blockIdx.x * 256 + threadIdx.x;
    if (i < N_NODES) {
        int r = g_rowstart[i] + g_part[blockIdx.x];
        g_rowstart[i] = r;
        g_cursor[i] = r;
    }
}

// ---------------- CSR fill ---------------------------------------------------
__global__ void fill_csr_kernel(const void* __restrict__ ei) {
    int e = blockIdx.x * blockDim.x + threadIdx.x;
    if (e >= N_EDGES) return;
    int s, d;
    load_edge(ei, e, g_is64, s, d);
    float w = g_dinv[s] * g_dinv[d];
    int slot = atomicAdd(&g_cursor[d], 1);
    g_csr[slot] = make_int2(s, __float_as_int(w));
}

// ---------------- tensor-core GEMM (bf16x3 fp32 emulation, fp16 out) --------
__device__ __forceinline__ void mma_bf16(float* c, const unsigned* a,
                                         unsigned b0, unsigned b1) {
    asm volatile(
        "mma.sync.aligned.m16n8k16.row.col.f32.bf16.bf16.f32 "
        "{%0,%1,%2,%3},{%4,%5,%6,%7},{%8,%9},{%0,%1,%2,%3};"
        : "+f"(c[0]), "+f"(c[1]), "+f"(c[2]), "+f"(c[3])
        : "r"(a[0]), "r"(a[1]), "r"(a[2]), "r"(a[3]), "r"(b0), "r"(b1));
}

template<int K, int NC, bool RELU_IN>
__global__ __launch_bounds__(256)
void mma_gemm_kernel(const float* __restrict__ A,
                     const unsigned* __restrict__ Wh,
                     const unsigned* __restrict__ Wl,
                     __half* __restrict__ out, int M) {
    constexpr int BK = 32;
    constexpr int STRIDE = 20;                 // words per row
    constexpr int WARPS_N = (NC == 128) ? 2 : 1;
    constexpr int WARPS_M = 8 / WARPS_N;       // 4 or 8
    constexpr int MT = 128 / (WARPS_M * 16);   // m16-tiles per warp: 2 or 1
    constexpr int NSHIFT = (NC == 128) ? 7 : 6;
    constexpr int WWORDS = 16 * NC;            // packed words per k-chunk

    __shared__ unsigned Ah[128 * STRIDE], Al[128 * STRIDE];
    __shared__ unsigned Bh[NC * STRIDE],  Bl[NC * STRIDE];

    int tid = threadIdx.x, wid = tid >> 5, lane = tid & 31;
    int g = lane >> 2, t4 = lane & 3;
    int warp_m = (wid % WARPS_M) * (MT * 16);
    int warp_n = (wid / WARPS_M) * 64;
    int m0 = blockIdx.x * 128;

    float acc[MT][8][4];
#pragma unroll
    for (int mt = 0; mt < MT; mt++)
#pragma unroll
        for (int nt = 0; nt < 8; nt++)
#pragma unroll
            for (int i = 0; i < 4; i++) acc[mt][nt][i] = 0.0f;

    for (int kk = 0; kk < K; kk += BK) {
        // ---- A tile: 128 rows x 32 cols, split on the fly ----
#pragma unroll
        for (int i = 0; i < 4; i++) {
            int idx = i * 256 + tid;
            int r = idx >> 3, c4 = idx & 7;
            int gm = m0 + r;
            float4 v = make_float4(0.f, 0.f, 0.f, 0.f);
            if (gm < M)
                v = *(const float4*)(A + (size_t)gm * K + kk + c4 * 4);
            if (RELU_IN) {
                v.x = fmaxf(v.x, 0.f); v.y = fmaxf(v.y, 0.f);
                v.z = fmaxf(v.z, 0.f); v.w = fmaxf(v.w, 0.f);
            }
            unsigned hx, lx, hy, ly, hz, lz, hw, lw;
            split_bf16(v.x, hx, lx); split_bf16(v.y, hy, ly);
            split_bf16(v.z, hz, lz); split_bf16(v.w, hw, lw);
            int base = r * STRIDE + c4 * 2;
            *(uint2*)&Ah[base] = make_uint2((hy << 16) | hx, (hw << 16) | hz);
            *(uint2*)&Al[base] = make_uint2((ly << 16) | lx, (lw << 16) | lz);
        }
        // ---- W tile: pure copy of pre-split packed words ----
        {
            const unsigned* wh = Wh + (size_t)(kk >> 1) * NC;
            const unsigned* wl = Wl + (size_t)(kk >> 1) * NC;
#pragma unroll
            for (int i = 0; i < WWORDS / 256; i++) {
                int idx = i * 256 + tid;
                int n = idx & (NC - 1), k2 = idx >> NSHIFT;
                Bh[n * STRIDE + k2] = wh[idx];
                Bl[n * STRIDE + k2] = wl[idx];
            }
        }
        __syncthreads();

#pragma unroll
        for (int ks = 0; ks < 2; ks++) {
            unsigned ah[MT][4], al[MT][4];
#pragma unroll
            for (int mt = 0; mt < MT; mt++) {
                int r0 = (warp_m + mt * 16 + g) * STRIDE + ks * 8 + t4;
                int r1 = (warp_m + mt * 16 + g + 8) * STRIDE + ks * 8 + t4;
                ah[mt][0] = Ah[r0];     ah[mt][1] = Ah[r1];
                ah[mt][2] = Ah[r0 + 4]; ah[mt][3] = Ah[r1 + 4];
                al[mt][0] = Al[r0];     al[mt][1] = Al[r1];
                al[mt][2] = Al[r0 + 4]; al[mt][3] = Al[r1 + 4];
            }
#pragma unroll
            for (int nt = 0; nt < 8; nt++) {
                int bi = (warp_n + nt * 8 + g) * STRIDE + ks * 8 + t4;
                unsigned bh0 = Bh[bi], bh1 = Bh[bi + 4];
                unsigned bl0 = Bl[bi], bl1 = Bl[bi + 4];
#pragma unroll
                for (int mt = 0; mt < MT; mt++) {
                    mma_bf16(acc[mt][nt], ah[mt], bh0, bh1);  // hi*hi
                    mma_bf16(acc[mt][nt], ah[mt], bl0, bl1);  // hi*lo
                    mma_bf16(acc[mt][nt], al[mt], bh0, bh1);  // lo*hi
                }
            }
        }
        __syncthreads();
    }

    // ---- epilogue: fp16 stores ----
#pragma unroll
    for (int mt = 0; mt < MT; mt++) {
        int r0 = m0 + warp_m + mt * 16 + g;
        int r1 = r0 + 8;
#pragma unroll
        for (int nt = 0; nt < 8; nt++) {
            int col = warp_n + nt * 8 + t4 * 2;
            if (r0 < M)
                *(__half2*)(out + (size_t)r0 * NC + col) =
                    __floats2half2_rn(acc[mt][nt][0], acc[mt][nt][1]);
            if (r1 < M)
                *(__half2*)(out + (size_t)r1 * NC + col) =
                    __floats2half2_rn(acc[mt][nt][2], acc[mt][nt][3]);
        }
    }
}

// ---------------- fp16 row-gather helper -------------------------------------
__device__ __forceinline__ float4 ld_h4(const __half* __restrict__ row, int lane) {
    uint2 u = __ldg((const uint2*)row + lane);
    float2 fa = __half22float2(*reinterpret_cast<__half2*>(&u.x));
    float2 fb = __half22float2(*reinterpret_cast<__half2*>(&u.y));
    return make_float4(fa.x, fa.y, fb.x, fb.y);
}

// ---------------- CSR aggregation: layer 1 (warp per node) ------------------
__global__ __launch_bounds__(256)
void agg1_kernel(const float* __restrict__ b1) {
    int node = (blockIdx.x * blockDim.x + threadIdx.x) >> 5;
    int lane = threadIdx.x & 31;
    if (node >= N_NODES) return;
    int beg = g_rowstart[node];
    int cnt = g_cnt[node];

    float4 acc = make_float4(0.f, 0.f, 0.f, 0.f);
    int j = 0;
    for (; j + 1 < cnt; j += 2) {
        int2 e0 = __ldg(&g_csr[beg + j]);
        int2 e1 = __ldg(&g_csr[beg + j + 1]);
        float w0 = __int_as_float(e0.y);
        float w1 = __int_as_float(e1.y);
        float4 v0 = ld_h4(g_h1h + (size_t)e0.x * HID_CH, lane);
        float4 v1 = ld_h4(g_h1h + (size_t)e1.x * HID_CH, lane);
        acc.x += w0 * v0.x + w1 * v1.x;
        acc.y += w0 * v0.y + w1 * v1.y;
        acc.z += w0 * v0.z + w1 * v1.z;
        acc.w += w0 * v0.w + w1 * v1.w;
    }
    if (j < cnt) {
        int2 e = __ldg(&g_csr[beg + j]);
        float w = __int_as_float(e.y);
        float4 v = ld_h4(g_h1h + (size_t)e.x * HID_CH, lane);
        acc.x += w * v.x; acc.y += w * v.y;
        acc.z += w * v.z; acc.w += w * v.w;
    }
    float di = g_dinv[node];
    float sw = di * di;
    float4 h = ld_h4(g_h1h + (size_t)node * HID_CH, lane);
    float4 b = ((const float4*)b1)[lane];
    acc.x += b.x + sw * h.x;
    acc.y += b.y + sw * h.y;
    acc.z += b.z + sw * h.z;
    acc.w += b.w + sw * h.w;
    ((float4*)(g_a1 + (size_t)node * HID_CH))[lane] = acc;
}

// ---------------- CSR aggregation: layer 2 (16 lanes per node) --------------
__global__ __launch_bounds__(256)
void agg2_kernel(const float* __restrict__ b2, float* __restrict__ out) {
    int node = (blockIdx.x * blockDim.x + threadIdx.x) >> 4;
    int lane = threadIdx.x & 15;
    if (node >= N_NODES) return;
    int beg = g_rowstart[node];
    int cnt = g_cnt[node];

    float4 acc = make_float4(0.f, 0.f, 0.f, 0.f);
    int j = 0;
    for (; j + 1 < cnt; j += 2) {
        int2 e0 = __ldg(&g_csr[beg + j]);
        int2 e1 = __ldg(&g_csr[beg + j + 1]);
        float w0 = __int_as_float(e0.y);
        float w1 = __int_as_float(e1.y);
        float4 v0 = ld_h4(g_h2h + (size_t)e0.x * OUT_CH, lane);
        float4 v1 = ld_h4(g_h2h + (size_t)e1.x * OUT_CH, lane);
        acc.x += w0 * v0.x + w1 * v1.x;
        acc.y += w0 * v0.y + w1 * v1.y;
        acc.z += w0 * v0.z + w1 * v1.z;
        acc.w += w0 * v0.w + w1 * v1.w;
    }
    if (j < cnt) {
        int2 e = __ldg(&g_csr[beg + j]);
        float w = __int_as_float(e.y);
        float4 v = ld_h4(g_h2h + (size_t)e.x * OUT_CH, lane);
        acc.x += w * v.x; acc.y += w * v.y;
        acc.z += w * v.z; acc.w += w * v.w;
    }
    float di = g_dinv[node];
    float sw = di * di;
    float4 h = ld_h4(g_h2h + (size_t)node * OUT_CH, lane);
    float4 b = ((const float4*)b2)[lane];
    acc.x += b.x + sw * h.x;
    acc.y += b.y + sw * h.y;
    acc.z += b.z + sw * h.z;
    acc.w += b.w + sw * h.w;
    ((float4*)(out + (size_t)node * OUT_CH))[lane] = acc;
}

// ---------------- launch ----------------------------------------------------
extern "C" void kernel_launch(void* const* d_in, const int* in_sizes, int n_in,
                              void* d_out, int out_size) {
    const float* x  = (const float*)d_in[0];
    const void*  ei = d_in[1];
    const float* W1 = (const float*)d_in[2];
    const float* b1 = (const float*)d_in[3];
    const float* W2 = (const float*)d_in[4];
    const float* b2 = (const float*)d_in[5];
    float* out = (float*)d_out;

    __half *p_h1h, *p_h2h; float* p_a1;
    unsigned *p_W1h, *p_W1l, *p_W2h, *p_W2l;
    cudaGetSymbolAddress((void**)&p_h1h, g_h1h);
    cudaGetSymbolAddress((void**)&p_a1,  g_a1);
    cudaGetSymbolAddress((void**)&p_h2h, g_h2h);
    cudaGetSymbolAddress((void**)&p_W1h, g_W1h);
    cudaGetSymbolAddress((void**)&p_W1l, g_W1l);
    cudaGetSymbolAddress((void**)&p_W2h, g_W2h);
    cudaGetSymbolAddress((void**)&p_W2l, g_W2l);

    // prep: counters + dtype + W split
    zero_detect_kernel<<<NB_SCAN, 256>>>((const unsigned*)ei);
    wsplit_kernel<<<((IN_CH / 2) * HID_CH + 255) / 256, 256>>>(W1, W2);
    count_deg_kernel<<<(N_EDGES + 255) / 256, 256>>>(ei);
    scan1_kernel<<<NB_SCAN, 256>>>();
    scan2_kernel<<<1, 512>>>();
    scan3_kernel<<<NB_SCAN, 256>>>();
    fill_csr_kernel<<<(N_EDGES + 255) / 256, 256>>>(ei);

    // layer 1: h1 = x @ W1 ; a1 = bias + norm-agg(h1)
    mma_gemm_kernel<IN_CH, HID_CH, false>
        <<<(N_NODES + 127) / 128, 256>>>(x, p_W1h, p_W1l, p_h1h, N_NODES);
    agg1_kernel<<<(N_NODES * 32 + 255) / 256, 256>>>(b1);

    // layer 2: h2 = relu(a1) @ W2 ; out = bias + norm-agg(h2)
    mma_gemm_kernel<HID_CH, OUT_CH, true>
        <<<(N_NODES + 127) / 128, 256>>>(p_a1, p_W2h, p_W2l, p_h2h, N_NODES);
    agg2_kernel<<<(N_NODES * 16 + 255) / 256, 256>>>(b2, out);
}

// round 5
// speedup vs baseline: 2.3484x; 1.1011x over previous
#include <cuda_runtime.h>
#include <cuda_fp16.h>

#define N_NODES 100000
#define N_EDGES 1600000
#define IN_CH   256
#define HID_CH  128
#define OUT_CH  64
#define NB_SCAN ((N_NODES + 255) / 256)   // 391

// ---------------- scratch (device globals; no cudaMalloc allowed) ----------
__device__ int      g_cnt     [N_NODES];
__device__ int      g_rowstart[N_NODES];
__device__ int      g_cursor  [N_NODES];
__device__ int      g_part    [512];
__device__ int2     g_csr     [N_EDGES];          // (src, weight-as-int)
__device__ float    g_dinv    [N_NODES];
__device__ __half   g_h1h[(size_t)N_NODES * HID_CH];   // x @ W1   (fp16)
__device__ __half   g_a1h[(size_t)N_NODES * HID_CH];   // aggregated layer-1 (fp16)
__device__ __half   g_h2h[(size_t)N_NODES * OUT_CH];   // relu(a1) @ W2 (fp16)
__device__ unsigned g_W1h[(IN_CH / 2) * HID_CH];   // pre-split bf16 hi packed
__device__ unsigned g_W1l[(IN_CH / 2) * HID_CH];
__device__ unsigned g_W2h[(HID_CH / 2) * OUT_CH];
__device__ unsigned g_W2l[(HID_CH / 2) * OUT_CH];
__device__ int      g_is64;

// ---------------- bf16 hi/lo split ------------------------------------------
__device__ __forceinline__ void split_bf16(float x, unsigned& h, unsigned& l) {
    unsigned xb = __float_as_uint(x);
    unsigned hr = (xb + 0x7FFFu + ((xb >> 16) & 1u)) >> 16;   // RN-even bf16
    float hf = __uint_as_float(hr << 16);
    float lf = x - hf;
    unsigned lb = __float_as_uint(lf);
    unsigned lr = (lb + 0x7FFFu + ((lb >> 16) & 1u)) >> 16;
    h = hr; l = lr;
}

// ---------------- prep: zero counters + dtype detect ------------------------
__global__ void zero_detect_kernel(const unsigned* __restrict__ w) {
    int n = blockIdx.x * blockDim.x + threadIdx.x;
    if (n < N_NODES) g_cnt[n] = 0;
    if (n == 0) {
        int is64 = 1;
        for (int i = 0; i < 64; i++)
            if (w[2 * i + 1] != 0u) { is64 = 0; break; }
        g_is64 = is64;
    }
}

__device__ __forceinline__ void load_edge(const void* ei, long long e, int is64,
                                          int& s, int& d) {
    if (is64) {
        const long long* p = (const long long*)ei;
        s = (int)p[e];
        d = (int)p[(long long)N_EDGES + e];
    } else {
        const int* p = (const int*)ei;
        s = p[e];
        d = p[(long long)N_EDGES + e];
    }
}

__global__ void count_deg_kernel(const void* __restrict__ ei) {
    int e = blockIdx.x * blockDim.x + threadIdx.x;
    if (e >= N_EDGES) return;
    int d;
    if (g_is64) d = (int)((const long long*)ei)[(long long)N_EDGES + e];
    else        d = ((const int*)ei)[(long long)N_EDGES + e];
    atomicAdd(&g_cnt[d], 1);
}

// ---------------- W pre-split (bf16 hi/lo, packed 2-k-per-word) -------------
__global__ void wsplit_kernel(const float* __restrict__ W1,
                              const float* __restrict__ W2) {
    int i = blockIdx.x * blockDim.x + threadIdx.x;
    if (i < (IN_CH / 2) * HID_CH) {
        int k2 = i / HID_CH, n = i % HID_CH;
        float w0 = W1[(size_t)(2 * k2) * HID_CH + n];
        float w1 = W1[(size_t)(2 * k2 + 1) * HID_CH + n];
        unsigned h0, l0, h1, l1;
        split_bf16(w0, h0, l0); split_bf16(w1, h1, l1);
        g_W1h[i] = (h1 << 16) | h0;
        g_W1l[i] = (l1 << 16) | l0;
    }
    if (i < (HID_CH / 2) * OUT_CH) {
        int k2 = i / OUT_CH, n = i % OUT_CH;
        float w0 = W2[(size_t)(2 * k2) * OUT_CH + n];
        float w1 = W2[(size_t)(2 * k2 + 1) * OUT_CH + n];
        unsigned h0, l0, h1, l1;
        split_bf16(w0, h0, l0); split_bf16(w1, h1, l1);
        g_W2h[i] = (h1 << 16) | h0;
        g_W2l[i] = (l1 << 16) | l0;
    }
}

// ---------------- scans (dinv fused into scan1) ------------------------------
__global__ void scan1_kernel() {
    __shared__ int sm[256];
    int tid = threadIdx.x;
    int i = blockIdx.x * 256 + tid;
    int v = (i < N_NODES) ? g_cnt[i] : 0;
    if (i < N_NODES) g_dinv[i] = rsqrtf((float)(v + 1));   // +1 self-loop
    sm[tid] = v;
    __syncthreads();
#pragma unroll
    for (int off = 1; off < 256; off <<= 1) {
        int t = (tid >= off) ? sm[tid - off] : 0;
        __syncthreads();
        sm[tid] += t;
        __syncthreads();
    }
    if (i < N_NODES) g_rowstart[i] = sm[tid] - v;
    if (tid == 255) g_part[blockIdx.x] = sm[tid];
}

__global__ void scan2_kernel() {
    __shared__ int sm[512];
    int tid = threadIdx.x;
    int v = (tid < NB_SCAN) ? g_part[tid] : 0;
    sm[tid] = v;
    __syncthreads();
#pragma unroll
    for (int off = 1; off < 512; off <<= 1) {
        int t = (tid >= off) ? sm[tid - off] : 0;
        __syncthreads();
        sm[tid] += t;
        __syncthreads();
    }
    if (tid < NB_SCAN) g_part[tid] = sm[tid] - v;
}

__global__ void scan3_kernel() {
    int i = blockIdx.x * 256 + threadIdx.x;
    if (i < N_NODES) {
        int r = g_rowstart[i] + g_part[blockIdx.x];
        g_rowstart[i] = r;
        g_cursor[i] = r;
    }
}

// ---------------- CSR fill ---------------------------------------------------
__global__ void fill_csr_kernel(const void* __restrict__ ei) {
    int e = blockIdx.x * blockDim.x + threadIdx.x;
    if (e >= N_EDGES) return;
    int s, d;
    load_edge(ei, e, g_is64, s, d);
    float w = g_dinv[s] * g_dinv[d];
    int slot = atomicAdd(&g_cursor[d], 1);
    g_csr[slot] = make_int2(s, __float_as_int(w));
}

// ---------------- tensor-core GEMM (bf16x3 fp32 emulation, fp16 out) --------
__device__ __forceinline__ void mma_bf16(float* c, const unsigned* a,
                                         unsigned b0, unsigned b1) {
    asm volatile(
        "mma.sync.aligned.m16n8k16.row.col.f32.bf16.bf16.f32 "
        "{%0,%1,%2,%3},{%4,%5,%6,%7},{%8,%9},{%0,%1,%2,%3};"
        : "+f"(c[0]), "+f"(c[1]), "+f"(c[2]), "+f"(c[3])
        : "r"(a[0]), "r"(a[1]), "r"(a[2]), "r"(a[3]), "r"(b0), "r"(b1));
}

template<int K, int NC, bool RELU_IN, bool A_HALF>
__global__ __launch_bounds__(256)
void mma_gemm_kernel(const void* __restrict__ A,
                     const unsigned* __restrict__ Wh,
                     const unsigned* __restrict__ Wl,
                     __half* __restrict__ out, int M) {
    constexpr int BK = 32;
    constexpr int STRIDE = 20;                 // words per row
    constexpr int WARPS_N = (NC == 128) ? 2 : 1;
    constexpr int WARPS_M = 8 / WARPS_N;       // 4 or 8
    constexpr int MT = 128 / (WARPS_M * 16);   // m16-tiles per warp: 2 or 1
    constexpr int NSHIFT = (NC == 128) ? 7 : 6;
    constexpr int WWORDS = 16 * NC;            // packed words per k-chunk

    __shared__ unsigned Ah[128 * STRIDE], Al[128 * STRIDE];
    __shared__ unsigned Bh[NC * STRIDE],  Bl[NC * STRIDE];

    int tid = threadIdx.x, wid = tid >> 5, lane = tid & 31;
    int g = lane >> 2, t4 = lane & 3;
    int warp_m = (wid % WARPS_M) * (MT * 16);
    int warp_n = (wid / WARPS_M) * 64;
    int m0 = blockIdx.x * 128;

    float acc[MT][8][4];
#pragma unroll
    for (int mt = 0; mt < MT; mt++)
#pragma unroll
        for (int nt = 0; nt < 8; nt++)
#pragma unroll
            for (int i = 0; i < 4; i++) acc[mt][nt][i] = 0.0f;

    for (int kk = 0; kk < K; kk += BK) {
        // ---- A tile: 128 rows x 32 cols, split on the fly ----
#pragma unroll
        for (int i = 0; i < 4; i++) {
            int idx = i * 256 + tid;
            int r = idx >> 3, c4 = idx & 7;
            int gm = m0 + r;
            float4 v = make_float4(0.f, 0.f, 0.f, 0.f);
            if (gm < M) {
                if (A_HALF) {
                    uint2 u = *(const uint2*)((const __half*)A +
                                              (size_t)gm * K + kk + c4 * 4);
                    float2 fa = __half22float2(*reinterpret_cast<__half2*>(&u.x));
                    float2 fb = __half22float2(*reinterpret_cast<__half2*>(&u.y));
                    v = make_float4(fa.x, fa.y, fb.x, fb.y);
                } else {
                    v = *(const float4*)((const float*)A +
                                         (size_t)gm * K + kk + c4 * 4);
                }
            }
            if (RELU_IN) {
                v.x = fmaxf(v.x, 0.f); v.y = fmaxf(v.y, 0.f);
                v.z = fmaxf(v.z, 0.f); v.w = fmaxf(v.w, 0.f);
            }
            unsigned hx, lx, hy, ly, hz, lz, hw, lw;
            split_bf16(v.x, hx, lx); split_bf16(v.y, hy, ly);
            split_bf16(v.z, hz, lz); split_bf16(v.w, hw, lw);
            int base = r * STRIDE + c4 * 2;
            *(uint2*)&Ah[base] = make_uint2((hy << 16) | hx, (hw << 16) | hz);
            *(uint2*)&Al[base] = make_uint2((ly << 16) | lx, (lw << 16) | lz);
        }
        // ---- W tile: pure copy of pre-split packed words ----
        {
            const unsigned* wh = Wh + (size_t)(kk >> 1) * NC;
            const unsigned* wl = Wl + (size_t)(kk >> 1) * NC;
#pragma unroll
            for (int i = 0; i < WWORDS / 256; i++) {
                int idx = i * 256 + tid;
                int n = idx & (NC - 1), k2 = idx >> NSHIFT;
                Bh[n * STRIDE + k2] = wh[idx];
                Bl[n * STRIDE + k2] = wl[idx];
            }
        }
        __syncthreads();

#pragma unroll
        for (int ks = 0; ks < 2; ks++) {
            unsigned ah[MT][4], al[MT][4];
#pragma unroll
            for (int mt = 0; mt < MT; mt++) {
                int r0 = (warp_m + mt * 16 + g) * STRIDE + ks * 8 + t4;
                int r1 = (warp_m + mt * 16 + g + 8) * STRIDE + ks * 8 + t4;
                ah[mt][0] = Ah[r0];     ah[mt][1] = Ah[r1];
                ah[mt][2] = Ah[r0 + 4]; ah[mt][3] = Ah[r1 + 4];
                al[mt][0] = Al[r0];     al[mt][1] = Al[r1];
                al[mt][2] = Al[r0 + 4]; al[mt][3] = Al[r1 + 4];
            }
#pragma unroll
            for (int nt = 0; nt < 8; nt++) {
                int bi = (warp_n + nt * 8 + g) * STRIDE + ks * 8 + t4;
                unsigned bh0 = Bh[bi], bh1 = Bh[bi + 4];
                unsigned bl0 = Bl[bi], bl1 = Bl[bi + 4];
#pragma unroll
                for (int mt = 0; mt < MT; mt++) {
                    mma_bf16(acc[mt][nt], ah[mt], bh0, bh1);  // hi*hi
                    mma_bf16(acc[mt][nt], ah[mt], bl0, bl1);  // hi*lo
                    mma_bf16(acc[mt][nt], al[mt], bh0, bh1);  // lo*hi
                }
            }
        }
        __syncthreads();
    }

    // ---- epilogue: fp16 stores ----
#pragma unroll
    for (int mt = 0; mt < MT; mt++) {
        int r0 = m0 + warp_m + mt * 16 + g;
        int r1 = r0 + 8;
#pragma unroll
        for (int nt = 0; nt < 8; nt++) {
            int col = warp_n + nt * 8 + t4 * 2;
            if (r0 < M)
                *(__half2*)(out + (size_t)r0 * NC + col) =
                    __floats2half2_rn(acc[mt][nt][0], acc[mt][nt][1]);
            if (r1 < M)
                *(__half2*)(out + (size_t)r1 * NC + col) =
                    __floats2half2_rn(acc[mt][nt][2], acc[mt][nt][3]);
        }
    }
}

// ---------------- fp16 row-gather helper -------------------------------------
__device__ __forceinline__ float4 ld_h4(const __half* __restrict__ row, int lane) {
    uint2 u = __ldg((const uint2*)row + lane);
    float2 fa = __half22float2(*reinterpret_cast<__half2*>(&u.x));
    float2 fb = __half22float2(*reinterpret_cast<__half2*>(&u.y));
    return make_float4(fa.x, fa.y, fb.x, fb.y);
}

// ---------------- CSR aggregation: layer 1 (warp per node, fp16 out) --------
__global__ __launch_bounds__(256)
void agg1_kernel(const float* __restrict__ b1) {
    int node = (blockIdx.x * blockDim.x + threadIdx.x) >> 5;
    int lane = threadIdx.x & 31;
    if (node >= N_NODES) return;
    int beg = g_rowstart[node];
    int cnt = g_cnt[node];

    float4 acc = make_float4(0.f, 0.f, 0.f, 0.f);
    int j = 0;
    for (; j + 1 < cnt; j += 2) {
        int2 e0 = __ldg(&g_csr[beg + j]);
        int2 e1 = __ldg(&g_csr[beg + j + 1]);
        float w0 = __int_as_float(e0.y);
        float w1 = __int_as_float(e1.y);
        float4 v0 = ld_h4(g_h1h + (size_t)e0.x * HID_CH, lane);
        float4 v1 = ld_h4(g_h1h + (size_t)e1.x * HID_CH, lane);
        acc.x += w0 * v0.x + w1 * v1.x;
        acc.y += w0 * v0.y + w1 * v1.y;
        acc.z += w0 * v0.z + w1 * v1.z;
        acc.w += w0 * v0.w + w1 * v1.w;
    }
    if (j < cnt) {
        int2 e = __ldg(&g_csr[beg + j]);
        float w = __int_as_float(e.y);
        float4 v = ld_h4(g_h1h + (size_t)e.x * HID_CH, lane);
        acc.x += w * v.x; acc.y += w * v.y;
        acc.z += w * v.z; acc.w += w * v.w;
    }
    float di = g_dinv[node];
    float sw = di * di;
    float4 h = ld_h4(g_h1h + (size_t)node * HID_CH, lane);
    float4 b = ((const float4*)b1)[lane];
    acc.x += b.x + sw * h.x;
    acc.y += b.y + sw * h.y;
    acc.z += b.z + sw * h.z;
    acc.w += b.w + sw * h.w;
    __half2 p0 = __floats2half2_rn(acc.x, acc.y);
    __half2 p1 = __floats2half2_rn(acc.z, acc.w);
    uint2 u;
    u.x = *reinterpret_cast<unsigned*>(&p0);
    u.y = *reinterpret_cast<unsigned*>(&p1);
    ((uint2*)(g_a1h + (size_t)node * HID_CH))[lane] = u;
}

// ---------------- CSR aggregation: layer 2 (16 lanes per node) --------------
__global__ __launch_bounds__(256)
void agg2_kernel(const float* __restrict__ b2, float* __restrict__ out) {
    int node = (blockIdx.x * blockDim.x + threadIdx.x) >> 4;
    int lane = threadIdx.x & 15;
    if (node >= N_NODES) return;
    int beg = g_rowstart[node];
    int cnt = g_cnt[node];

    float4 acc = make_float4(0.f, 0.f, 0.f, 0.f);
    int j = 0;
    for (; j + 1 < cnt; j += 2) {
        int2 e0 = __ldg(&g_csr[beg + j]);
        int2 e1 = __ldg(&g_csr[beg + j + 1]);
        float w0 = __int_as_float(e0.y);
        float w1 = __int_as_float(e1.y);
        float4 v0 = ld_h4(g_h2h + (size_t)e0.x * OUT_CH, lane);
        float4 v1 = ld_h4(g_h2h + (size_t)e1.x * OUT_CH, lane);
        acc.x += w0 * v0.x + w1 * v1.x;
        acc.y += w0 * v0.y + w1 * v1.y;
        acc.z += w0 * v0.z + w1 * v1.z;
        acc.w += w0 * v0.w + w1 * v1.w;
    }
    if (j < cnt) {
        int2 e = __ldg(&g_csr[beg + j]);
        float w = __int_as_float(e.y);
        float4 v = ld_h4(g_h2h + (size_t)e.x * OUT_CH, lane);
        acc.x += w * v.x; acc.y += w * v.y;
        acc.z += w * v.z; acc.w += w * v.w;
    }
    float di = g_dinv[node];
    float sw = di * di;
    float4 h = ld_h4(g_h2h + (size_t)node * OUT_CH, lane);
    float4 b = ((const float4*)b2)[lane];
    acc.x += b.x + sw * h.x;
    acc.y += b.y + sw * h.y;
    acc.z += b.z + sw * h.z;
    acc.w += b.w + sw * h.w;
    ((float4*)(out + (size_t)node * OUT_CH))[lane] = acc;
}

// ---------------- launch ----------------------------------------------------
extern "C" void kernel_launch(void* const* d_in, const int* in_sizes, int n_in,
                              void* d_out, int out_size) {
    const float* x  = (const float*)d_in[0];
    const void*  ei = d_in[1];
    const float* W1 = (const float*)d_in[2];
    const float* b1 = (const float*)d_in[3];
    const float* W2 = (const float*)d_in[4];
    const float* b2 = (const float*)d_in[5];
    float* out = (float*)d_out;

    __half *p_h1h, *p_a1h, *p_h2h;
    unsigned *p_W1h, *p_W1l, *p_W2h, *p_W2l;
    cudaGetSymbolAddress((void**)&p_h1h, g_h1h);
    cudaGetSymbolAddress((void**)&p_a1h, g_a1h);
    cudaGetSymbolAddress((void**)&p_h2h, g_h2h);
    cudaGetSymbolAddress((void**)&p_W1h, g_W1h);
    cudaGetSymbolAddress((void**)&p_W1l, g_W1l);
    cudaGetSymbolAddress((void**)&p_W2h, g_W2h);
    cudaGetSymbolAddress((void**)&p_W2l, g_W2l);

    // one-time side stream + fork/join events (resource creation only;
    // the launched work is identical on every call)
    static cudaStream_t s_side = nullptr;
    static cudaEvent_t  s_fork = nullptr, s_join = nullptr;
    if (s_side == nullptr) {
        cudaStreamCreateWithFlags(&s_side, cudaStreamNonBlocking);
        cudaEventCreateWithFlags(&s_fork, cudaEventDisableTiming);
        cudaEventCreateWithFlags(&s_join, cudaEventDisableTiming);
    }

    // fork: CSR-build branch runs concurrently with wsplit + GEMM1
    cudaEventRecord(s_fork, 0);
    cudaStreamWaitEvent(s_side, s_fork, 0);

    // --- side branch: edge prep -> CSR ---
    zero_detect_kernel<<<NB_SCAN, 256, 0, s_side>>>((const unsigned*)ei);
    count_deg_kernel<<<(N_EDGES + 255) / 256, 256, 0, s_side>>>(ei);
    scan1_kernel<<<NB_SCAN, 256, 0, s_side>>>();
    scan2_kernel<<<1, 512, 0, s_side>>>();
    scan3_kernel<<<NB_SCAN, 256, 0, s_side>>>();
    fill_csr_kernel<<<(N_EDGES + 255) / 256, 256, 0, s_side>>>(ei);
    cudaEventRecord(s_join, s_side);

    // --- main branch: W split + GEMM1 ---
    wsplit_kernel<<<((IN_CH / 2) * HID_CH + 255) / 256, 256>>>(W1, W2);
    mma_gemm_kernel<IN_CH, HID_CH, false, false>
        <<<(N_NODES + 127) / 128, 256>>>(x, p_W1h, p_W1l, p_h1h, N_NODES);

    // join: aggregation needs both CSR and h1
    cudaStreamWaitEvent(0, s_join, 0);

    agg1_kernel<<<(N_NODES * 32 + 255) / 256, 256>>>(b1);
    mma_gemm_kernel<HID_CH, OUT_CH, true, true>
        <<<(N_NODES + 127) / 128, 256>>>(p_a1h, p_W2h, p_W2l, p_h2h, N_NODES);
    agg2_kernel<<<(N_NODES * 16 + 255) / 256, 256>>>(b2, out);
}

// round 7
// speedup vs baseline: 2.8029x; 1.1935x over previous
#include <cuda_runtime.h>
#include <cuda_fp16.h>

#define N_NODES 100000
#define N_EDGES 1600000
#define IN_CH   256
#define HID_CH  128
#define OUT_CH  64
#define NB_SCAN ((N_NODES + 255) / 256)   // 391

// ---------------- scratch (device globals; no cudaMalloc allowed) ----------
__device__ int      g_cnt     [N_NODES];
__device__ int      g_rowstart[N_NODES];
__device__ int      g_cursor  [N_NODES];
__device__ int      g_part    [512];
__device__ int2     g_csr     [N_EDGES];          // (src, weight-as-int)
__device__ float    g_dinv    [N_NODES];
__device__ __half   g_h1h[(size_t)N_NODES * HID_CH];   // x @ W1   (fp16)
__device__ __half   g_a1h[(size_t)N_NODES * HID_CH];   // aggregated layer-1 (fp16)
__device__ __half   g_h2h[(size_t)N_NODES * OUT_CH];   // relu(a1) @ W2 (fp16)
__device__ unsigned g_W1p[(IN_CH / 2) * HID_CH];   // fp16 packed, 2 k per word
__device__ unsigned g_W2p[(HID_CH / 2) * OUT_CH];
__device__ int      g_is64;

// ---------------- prep: zero counters + dtype detect ------------------------
__global__ void zero_detect_kernel(const unsigned* __restrict__ w) {
    int n = blockIdx.x * blockDim.x + threadIdx.x;
    if (n < N_NODES) g_cnt[n] = 0;
    if (n == 0) {
        int is64 = 1;
        for (int i = 0; i < 64; i++)
            if (w[2 * i + 1] != 0u) { is64 = 0; break; }
        g_is64 = is64;
    }
}

__device__ __forceinline__ void load_edge(const void* ei, long long e, int is64,
                                          int& s, int& d) {
    if (is64) {
        const long long* p = (const long long*)ei;
        s = (int)p[e];
        d = (int)p[(long long)N_EDGES + e];
    } else {
        const int* p = (const int*)ei;
        s = p[e];
        d = p[(long long)N_EDGES + e];
    }
}

__global__ void count_deg_kernel(const void* __restrict__ ei) {
    int e = blockIdx.x * blockDim.x + threadIdx.x;
    if (e >= N_EDGES) return;
    int d;
    if (g_is64) d = (int)((const long long*)ei)[(long long)N_EDGES + e];
    else        d = ((const int*)ei)[(long long)N_EDGES + e];
    atomicAdd(&g_cnt[d], 1);
}

// ---------------- W pack (fp16, 2 k per word, n-fastest source) -------------
__global__ void wpack_kernel(const float* __restrict__ W1,
                             const float* __restrict__ W2) {
    int i = blockIdx.x * blockDim.x + threadIdx.x;
    if (i < (IN_CH / 2) * HID_CH) {
        int k2 = i / HID_CH, n = i % HID_CH;
        float w0 = W1[(size_t)(2 * k2) * HID_CH + n];
        float w1 = W1[(size_t)(2 * k2 + 1) * HID_CH + n];
        __half2 p = __floats2half2_rn(w0, w1);   // low = even k, high = odd k
        g_W1p[i] = *reinterpret_cast<unsigned*>(&p);
    }
    if (i < (HID_CH / 2) * OUT_CH) {
        int k2 = i / OUT_CH, n = i % OUT_CH;
        float w0 = W2[(size_t)(2 * k2) * OUT_CH + n];
        float w1 = W2[(size_t)(2 * k2 + 1) * OUT_CH + n];
        __half2 p = __floats2half2_rn(w0, w1);
        g_W2p[i] = *reinterpret_cast<unsigned*>(&p);
    }
}

// ---------------- scans (dinv fused into scan1) ------------------------------
__global__ void scan1_kernel() {
    __shared__ int sm[256];
    int tid = threadIdx.x;
    int i = blockIdx.x * 256 + tid;
    int v = (i < N_NODES) ? g_cnt[i] : 0;
    if (i < N_NODES) g_dinv[i] = rsqrtf((float)(v + 1));   // +1 self-loop
    sm[tid] = v;
    __syncthreads();
#pragma unroll
    for (int off = 1; off < 256; off <<= 1) {
        int t = (tid >= off) ? sm[tid - off] : 0;
        __syncthreads();
        sm[tid] += t;
        __syncthreads();
    }
    if (i < N_NODES) g_rowstart[i] = sm[tid] - v;
    if (tid == 255) g_part[blockIdx.x] = sm[tid];
}

__global__ void scan2_kernel() {
    __shared__ int sm[512];
    int tid = threadIdx.x;
    int v = (tid < NB_SCAN) ? g_part[tid] : 0;
    sm[tid] = v;
    __syncthreads();
#pragma unroll
    for (int off = 1; off < 512; off <<= 1) {
        int t = (tid >= off) ? sm[tid - off] : 0;
        __syncthreads();
        sm[tid] += t;
        __syncthreads();
    }
    if (tid < NB_SCAN) g_part[tid] = sm[tid] - v;
}

__global__ void scan3_kernel() {
    int i = blockIdx.x * 256 + threadIdx.x;
    if (i < N_NODES) {
        int r = g_rowstart[i] + g_part[blockIdx.x];
        g_rowstart[i] = r;
        g_cursor[i] = r;
    }
}

// ---------------- CSR fill ---------------------------------------------------
__global__ void fill_csr_kernel(const void* __restrict__ ei) {
    int e = blockIdx.x * blockDim.x + threadIdx.x;
    if (e >= N_EDGES) return;
    int s, d;
    load_edge(ei, e, g_is64, s, d);
    float w = g_dinv[s] * g_dinv[d];
    int slot = atomicAdd(&g_cursor[d], 1);
    g_csr[slot] = make_int2(s, __float_as_int(w));
}

// ---------------- tensor-core GEMM (fp16, fp32 accum, fp16 out) -------------
__device__ __forceinline__ void mma_f16(float* c, const unsigned* a,
                                        unsigned b0, unsigned b1) {
    asm volatile(
        "mma.sync.aligned.m16n8k16.row.col.f32.f16.f16.f32 "
        "{%0,%1,%2,%3},{%4,%5,%6,%7},{%8,%9},{%0,%1,%2,%3};"
        : "+f"(c[0]), "+f"(c[1]), "+f"(c[2]), "+f"(c[3])
        : "r"(a[0]), "r"(a[1]), "r"(a[2]), "r"(a[3]), "r"(b0), "r"(b1));
}

template<int K, int NC, bool RELU_IN, bool A_HALF>
__global__ __launch_bounds__(256)
void mma_gemm_kernel(const void* __restrict__ A,
                     const unsigned* __restrict__ Wp,
                     __half* __restrict__ out, int M) {
    constexpr int STRIDE = 20;                 // words per row (16 data + 4 pad)
    constexpr int WARPS_N = (NC == 128) ? 2 : 1;
    constexpr int WARPS_M = 8 / WARPS_N;       // 4 or 8
    constexpr int MT = 128 / (WARPS_M * 16);   // m16-tiles per warp: 2 or 1
    constexpr int NSHIFT = (NC == 128) ? 7 : 6;
    constexpr int WWORDS = 16 * NC;            // packed words per 32-k chunk

    __shared__ unsigned As[128 * STRIDE];
    __shared__ unsigned Bs[NC * STRIDE];

    int tid = threadIdx.x, wid = tid >> 5, lane = tid & 31;
    int g = lane >> 2, t4 = lane & 3;
    int warp_m = (wid % WARPS_M) * (MT * 16);
    int warp_n = (wid / WARPS_M) * 64;
    int m0 = blockIdx.x * 128;

    float acc[MT][8][4];
#pragma unroll
    for (int mt = 0; mt < MT; mt++)
#pragma unroll
        for (int nt = 0; nt < 8; nt++)
#pragma unroll
            for (int i = 0; i < 4; i++) acc[mt][nt][i] = 0.0f;

    for (int kk = 0; kk < K; kk += 32) {
        // ---- A tile: 128 rows x 32 k, fp16 convert/copy ----
#pragma unroll
        for (int i = 0; i < 4; i++) {
            int idx = i * 256 + tid;
            int r = idx >> 3, c4 = idx & 7;    // c4: float4/uint2 group of 4 k
            int gm = m0 + r;
            uint2 w = make_uint2(0u, 0u);
            if (gm < M) {
                if (A_HALF) {
                    w = *(const uint2*)((const __half*)A +
                                        (size_t)gm * K + kk + c4 * 4);
                    if (RELU_IN) {
                        __half2 zero = __floats2half2_rn(0.f, 0.f);
                        __half2 a0 = __hmax2(*reinterpret_cast<__half2*>(&w.x), zero);
                        __half2 a1 = __hmax2(*reinterpret_cast<__half2*>(&w.y), zero);
                        w.x = *reinterpret_cast<unsigned*>(&a0);
                        w.y = *reinterpret_cast<unsigned*>(&a1);
                    }
                } else {
                    float4 v = *(const float4*)((const float*)A +
                                                (size_t)gm * K + kk + c4 * 4);
                    if (RELU_IN) {
                        v.x = fmaxf(v.x, 0.f); v.y = fmaxf(v.y, 0.f);
                        v.z = fmaxf(v.z, 0.f); v.w = fmaxf(v.w, 0.f);
                    }
                    __half2 p0 = __floats2half2_rn(v.x, v.y);
                    __half2 p1 = __floats2half2_rn(v.z, v.w);
                    w.x = *reinterpret_cast<unsigned*>(&p0);
                    w.y = *reinterpret_cast<unsigned*>(&p1);
                }
            }
            *(uint2*)&As[r * STRIDE + c4 * 2] = w;
        }
        // ---- B tile: pure copy of pre-packed words ----
        {
            const unsigned* wp = Wp + (size_t)(kk >> 1) * NC;
#pragma unroll
            for (int i = 0; i < WWORDS / 256; i++) {
                int idx = i * 256 + tid;
                int n = idx & (NC - 1), k2 = idx >> NSHIFT;
                Bs[n * STRIDE + k2] = wp[idx];
            }
        }
        __syncthreads();

#pragma unroll
        for (int ks = 0; ks < 2; ks++) {
            unsigned a[MT][4];
#pragma unroll
            for (int mt = 0; mt < MT; mt++) {
                int r0 = (warp_m + mt * 16 + g) * STRIDE + ks * 8 + t4;
                int r1 = (warp_m + mt * 16 + g + 8) * STRIDE + ks * 8 + t4;
                a[mt][0] = As[r0];     a[mt][1] = As[r1];
                a[mt][2] = As[r0 + 4]; a[mt][3] = As[r1 + 4];
            }
#pragma unroll
            for (int nt = 0; nt < 8; nt++) {
                int bi = (warp_n + nt * 8 + g) * STRIDE + ks * 8 + t4;
                unsigned b0 = Bs[bi], b1 = Bs[bi + 4];
#pragma unroll
                for (int mt = 0; mt < MT; mt++)
                    mma_f16(acc[mt][nt], a[mt], b0, b1);
            }
        }
        __syncthreads();
    }

    // ---- epilogue: fp16 stores ----
#pragma unroll
    for (int mt = 0; mt < MT; mt++) {
        int r0 = m0 + warp_m + mt * 16 + g;
        int r1 = r0 + 8;
#pragma unroll
        for (int nt = 0; nt < 8; nt++) {
            int col = warp_n + nt * 8 + t4 * 2;
            if (r0 < M)
                *(__half2*)(out + (size_t)r0 * NC + col) =
                    __floats2half2_rn(acc[mt][nt][0], acc[mt][nt][1]);
            if (r1 < M)
                *(__half2*)(out + (size_t)r1 * NC + col) =
                    __floats2half2_rn(acc[mt][nt][2], acc[mt][nt][3]);
        }
    }
}

// ---------------- fp16 row-gather helper -------------------------------------
__device__ __forceinline__ float4 ld_h4(const __half* __restrict__ row, int lane) {
    uint2 u = __ldg((const uint2*)row + lane);
    float2 fa = __half22float2(*reinterpret_cast<__half2*>(&u.x));
    float2 fb = __half22float2(*reinterpret_cast<__half2*>(&u.y));
    return make_float4(fa.x, fa.y, fb.x, fb.y);
}

// ---------------- CSR aggregation: layer 1 (warp per node, fp16 out) --------
__global__ __launch_bounds__(256)
void agg1_kernel(const float* __restrict__ b1) {
    int node = (blockIdx.x * blockDim.x + threadIdx.x) >> 5;
    int lane = threadIdx.x & 31;
    if (node >= N_NODES) return;
    int beg = g_rowstart[node];
    int cnt = g_cnt[node];

    float4 acc = make_float4(0.f, 0.f, 0.f, 0.f);
    int j = 0;
    for (; j + 1 < cnt; j += 2) {
        int2 e0 = __ldg(&g_csr[beg + j]);
        int2 e1 = __ldg(&g_csr[beg + j + 1]);
        float w0 = __int_as_float(e0.y);
        float w1 = __int_as_float(e1.y);
        float4 v0 = ld_h4(g_h1h + (size_t)e0.x * HID_CH, lane);
        float4 v1 = ld_h4(g_h1h + (size_t)e1.x * HID_CH, lane);
        acc.x += w0 * v0.x + w1 * v1.x;
        acc.y += w0 * v0.y + w1 * v1.y;
        acc.z += w0 * v0.z + w1 * v1.z;
        acc.w += w0 * v0.w + w1 * v1.w;
    }
    if (j < cnt) {
        int2 e = __ldg(&g_csr[beg + j]);
        float w = __int_as_float(e.y);
        float4 v = ld_h4(g_h1h + (size_t)e.x * HID_CH, lane);
        acc.x += w * v.x; acc.y += w * v.y;
        acc.z += w * v.z; acc.w += w * v.w;
    }
    float di = g_dinv[node];
    float sw = di * di;
    float4 h = ld_h4(g_h1h + (size_t)node * HID_CH, lane);
    float4 b = ((const float4*)b1)[lane];
    acc.x += b.x + sw * h.x;
    acc.y += b.y + sw * h.y;
    acc.z += b.z + sw * h.z;
    acc.w += b.w + sw * h.w;
    __half2 p0 = __floats2half2_rn(acc.x, acc.y);
    __half2 p1 = __floats2half2_rn(acc.z, acc.w);
    uint2 u;
    u.x = *reinterpret_cast<unsigned*>(&p0);
    u.y = *reinterpret_cast<unsigned*>(&p1);
    ((uint2*)(g_a1h + (size_t)node * HID_CH))[lane] = u;
}

// ---------------- CSR aggregation: layer 2 (16 lanes per node) --------------
__global__ __launch_bounds__(256)
void agg2_kernel(const float* __restrict__ b2, float* __restrict__ out) {
    int node = (blockIdx.x * blockDim.x + threadIdx.x) >> 4;
    int lane = threadIdx.x & 15;
    if (node >= N_NODES) return;
    int beg = g_rowstart[node];
    int cnt = g_cnt[node];

    float4 acc = make_float4(0.f, 0.f, 0.f, 0.f);
    int j = 0;
    for (; j + 1 < cnt; j += 2) {
        int2 e0 = __ldg(&g_csr[beg + j]);
        int2 e1 = __ldg(&g_csr[beg + j + 1]);
        float w0 = __int_as_float(e0.y);
        float w1 = __int_as_float(e1.y);
        float4 v0 = ld_h4(g_h2h + (size_t)e0.x * OUT_CH, lane);
        float4 v1 = ld_h4(g_h2h + (size_t)e1.x * OUT_CH, lane);
        acc.x += w0 * v0.x + w1 * v1.x;
        acc.y += w0 * v0.y + w1 * v1.y;
        acc.z += w0 * v0.z + w1 * v1.z;
        acc.w += w0 * v0.w + w1 * v1.w;
    }
    if (j < cnt) {
        int2 e = __ldg(&g_csr[beg + j]);
        float w = __int_as_float(e.y);
        float4 v = ld_h4(g_h2h + (size_t)e.x * OUT_CH, lane);
        acc.x += w * v.x; acc.y += w * v.y;
        acc.z += w * v.z; acc.w += w * v.w;
    }
    float di = g_dinv[node];
    float sw = di * di;
    float4 h = ld_h4(g_h2h + (size_t)node * OUT_CH, lane);
    float4 b = ((const float4*)b2)[lane];
    acc.x += b.x + sw * h.x;
    acc.y += b.y + sw * h.y;
    acc.z += b.z + sw * h.z;
    acc.w += b.w + sw * h.w;
    ((float4*)(out + (size_t)node * OUT_CH))[lane] = acc;
}

// ---------------- launch ----------------------------------------------------
extern "C" void kernel_launch(void* const* d_in, const int* in_sizes, int n_in,
                              void* d_out, int out_size) {
    const float* x  = (const float*)d_in[0];
    const void*  ei = d_in[1];
    const float* W1 = (const float*)d_in[2];
    const float* b1 = (const float*)d_in[3];
    const float* W2 = (const float*)d_in[4];
    const float* b2 = (const float*)d_in[5];
    float* out = (float*)d_out;

    __half *p_h1h, *p_a1h, *p_h2h;
    unsigned *p_W1p, *p_W2p;
    cudaGetSymbolAddress((void**)&p_h1h, g_h1h);
    cudaGetSymbolAddress((void**)&p_a1h, g_a1h);
    cudaGetSymbolAddress((void**)&p_h2h, g_h2h);
    cudaGetSymbolAddress((void**)&p_W1p, g_W1p);
    cudaGetSymbolAddress((void**)&p_W2p, g_W2p);

    static cudaStream_t s_side = nullptr;
    static cudaEvent_t  s_fork = nullptr, s_join = nullptr;
    if (s_side == nullptr) {
        cudaStreamCreateWithFlags(&s_side, cudaStreamNonBlocking);
        cudaEventCreateWithFlags(&s_fork, cudaEventDisableTiming);
        cudaEventCreateWithFlags(&s_join, cudaEventDisableTiming);
    }

    // fork: CSR-build branch runs concurrently with wpack + GEMM1
    cudaEventRecord(s_fork, 0);
    cudaStreamWaitEvent(s_side, s_fork, 0);

    // --- side branch: edge prep -> CSR ---
    zero_detect_kernel<<<NB_SCAN, 256, 0, s_side>>>((const unsigned*)ei);
    count_deg_kernel<<<(N_EDGES + 255) / 256, 256, 0, s_side>>>(ei);
    scan1_kernel<<<NB_SCAN, 256, 0, s_side>>>();
    scan2_kernel<<<1, 512, 0, s_side>>>();
    scan3_kernel<<<NB_SCAN, 256, 0, s_side>>>();
    fill_csr_kernel<<<(N_EDGES + 255) / 256, 256, 0, s_side>>>(ei);
    cudaEventRecord(s_join, s_side);

    // --- main branch: W pack + GEMM1 ---
    wpack_kernel<<<((IN_CH / 2) * HID_CH + 255) / 256, 256>>>(W1, W2);
    mma_gemm_kernel<IN_CH, HID_CH, false, false>
        <<<(N_NODES + 127) / 128, 256>>>(x, p_W1p, p_h1h, N_NODES);

    // join: aggregation needs both CSR and h1
    cudaStreamWaitEvent(0, s_join, 0);

    agg1_kernel<<<(N_NODES * 32 + 255) / 256, 256>>>(b1);
    mma_gemm_kernel<HID_CH, OUT_CH, true, true>
        <<<(N_NODES + 127) / 128, 256>>>(p_a1h, p_W2p, p_h2h, N_NODES);
    agg2_kernel<<<(N_NODES * 16 + 255) / 256, 256>>>(b2, out);
}

// round 8
// speedup vs baseline: 2.8097x; 1.0024x over previous
#include <cuda_runtime.h>
#include <cuda_fp16.h>

#define N_NODES 100000
#define N_EDGES 1600000
#define IN_CH   256
#define HID_CH  128
#define OUT_CH  64
#define NB_SCAN ((N_NODES + 255) / 256)   // 391
#define HALF_N  50048                     // 391*128 = nice block multiple

// ---------------- scratch (device globals; no cudaMalloc allowed) ----------
__device__ int      g_cnt     [N_NODES];
__device__ int      g_rowstart[N_NODES];
__device__ int      g_cursor  [N_NODES];
__device__ int      g_part    [512];
__device__ int2     g_csr     [N_EDGES];          // (src, weight-as-int)
__device__ float    g_dinv    [N_NODES];
__device__ __half   g_h1h[(size_t)N_NODES * HID_CH];   // x @ W1   (fp16)
__device__ __half   g_a1h[(size_t)N_NODES * HID_CH];   // aggregated layer-1 (fp16)
__device__ __half   g_h2h[(size_t)N_NODES * OUT_CH];   // relu(a1) @ W2 (fp16)
__device__ unsigned g_W1p[(IN_CH / 2) * HID_CH];   // fp16 packed, 2 k per word
__device__ unsigned g_W2p[(HID_CH / 2) * OUT_CH];
__device__ int      g_is64;

// ---------------- prep: zero counters + dtype detect ------------------------
__global__ void zero_detect_kernel(const unsigned* __restrict__ w) {
    int n = blockIdx.x * blockDim.x + threadIdx.x;
    if (n < N_NODES) g_cnt[n] = 0;
    if (n == 0) {
        int is64 = 1;
        for (int i = 0; i < 64; i++)
            if (w[2 * i + 1] != 0u) { is64 = 0; break; }
        g_is64 = is64;
    }
}

__device__ __forceinline__ void load_edge(const void* ei, long long e, int is64,
                                          int& s, int& d) {
    if (is64) {
        const long long* p = (const long long*)ei;
        s = (int)p[e];
        d = (int)p[(long long)N_EDGES + e];
    } else {
        const int* p = (const int*)ei;
        s = p[e];
        d = p[(long long)N_EDGES + e];
    }
}

// 4 edges per thread
__global__ void count_deg_kernel(const void* __restrict__ ei) {
    int t = blockIdx.x * blockDim.x + threadIdx.x;
    if (t >= N_EDGES / 4) return;
    int d0, d1, d2, d3;
    if (g_is64) {
        const longlong2* p =
            (const longlong2*)((const long long*)ei + N_EDGES);
        longlong2 a = p[2 * t], b = p[2 * t + 1];
        d0 = (int)a.x; d1 = (int)a.y; d2 = (int)b.x; d3 = (int)b.y;
    } else {
        const int4* p = (const int4*)((const int*)ei + N_EDGES);
        int4 a = p[t];
        d0 = a.x; d1 = a.y; d2 = a.z; d3 = a.w;
    }
    atomicAdd(&g_cnt[d0], 1);
    atomicAdd(&g_cnt[d1], 1);
    atomicAdd(&g_cnt[d2], 1);
    atomicAdd(&g_cnt[d3], 1);
}

// ---------------- W pack (fp16, 2 k per word, n-fastest source) -------------
__global__ void wpack_kernel(const float* __restrict__ W1,
                             const float* __restrict__ W2) {
    int i = blockIdx.x * blockDim.x + threadIdx.x;
    if (i < (IN_CH / 2) * HID_CH) {
        int k2 = i / HID_CH, n = i % HID_CH;
        float w0 = W1[(size_t)(2 * k2) * HID_CH + n];
        float w1 = W1[(size_t)(2 * k2 + 1) * HID_CH + n];
        __half2 p = __floats2half2_rn(w0, w1);
        g_W1p[i] = *reinterpret_cast<unsigned*>(&p);
    }
    if (i < (HID_CH / 2) * OUT_CH) {
        int k2 = i / OUT_CH, n = i % OUT_CH;
        float w0 = W2[(size_t)(2 * k2) * OUT_CH + n];
        float w1 = W2[(size_t)(2 * k2 + 1) * OUT_CH + n];
        __half2 p = __floats2half2_rn(w0, w1);
        g_W2p[i] = *reinterpret_cast<unsigned*>(&p);
    }
}

// ---------------- scans (dinv fused into scan1; scan2 fused into scan23) ----
__global__ void scan1_kernel() {
    __shared__ int sm[256];
    int tid = threadIdx.x;
    int i = blockIdx.x * 256 + tid;
    int v = (i < N_NODES) ? g_cnt[i] : 0;
    if (i < N_NODES) g_dinv[i] = rsqrtf((float)(v + 1));   // +1 self-loop
    sm[tid] = v;
    __syncthreads();
#pragma unroll
    for (int off = 1; off < 256; off <<= 1) {
        int t = (tid >= off) ? sm[tid - off] : 0;
        __syncthreads();
        sm[tid] += t;
        __syncthreads();
    }
    if (i < N_NODES) g_rowstart[i] = sm[tid] - v;
    if (tid == 255) g_part[blockIdx.x] = sm[tid];
}

// each block computes its own cross-block base (sum of g_part[0..bid-1])
__global__ void scan23_kernel() {
    __shared__ int sm[256];
    int tid = threadIdx.x;
    int v = 0;
    for (int i = tid; i < blockIdx.x; i += 256) v += g_part[i];
    sm[tid] = v;
    __syncthreads();
#pragma unroll
    for (int off = 128; off > 0; off >>= 1) {
        if (tid < off) sm[tid] += sm[tid + off];
        __syncthreads();
    }
    int base = sm[0];
    int i = blockIdx.x * 256 + tid;
    if (i < N_NODES) {
        int r = g_rowstart[i] + base;
        g_rowstart[i] = r;
        g_cursor[i] = r;
    }
}

// ---------------- CSR fill (2 edges per thread) ------------------------------
__global__ void fill_csr_kernel(const void* __restrict__ ei) {
    int t = blockIdx.x * blockDim.x + threadIdx.x;
    if (t >= N_EDGES / 2) return;
    int s0, d0, s1, d1;
    if (g_is64) {
        const longlong2* ps = (const longlong2*)ei;
        const longlong2* pd = (const longlong2*)((const long long*)ei + N_EDGES);
        longlong2 a = ps[t], b = pd[t];
        s0 = (int)a.x; s1 = (int)a.y;
        d0 = (int)b.x; d1 = (int)b.y;
    } else {
        const int2* ps = (const int2*)ei;
        const int2* pd = (const int2*)((const int*)ei + N_EDGES);
        int2 a = ps[t], b = pd[t];
        s0 = a.x; s1 = a.y;
        d0 = b.x; d1 = b.y;
    }
    float w0 = g_dinv[s0] * g_dinv[d0];
    float w1 = g_dinv[s1] * g_dinv[d1];
    int slot0 = atomicAdd(&g_cursor[d0], 1);
    g_csr[slot0] = make_int2(s0, __float_as_int(w0));
    int slot1 = atomicAdd(&g_cursor[d1], 1);
    g_csr[slot1] = make_int2(s1, __float_as_int(w1));
}

// ---------------- tensor-core GEMM (fp16, fp32 accum, fp16 out) -------------
__device__ __forceinline__ void mma_f16(float* c, const unsigned* a,
                                        unsigned b0, unsigned b1) {
    asm volatile(
        "mma.sync.aligned.m16n8k16.row.col.f32.f16.f16.f32 "
        "{%0,%1,%2,%3},{%4,%5,%6,%7},{%8,%9},{%0,%1,%2,%3};"
        : "+f"(c[0]), "+f"(c[1]), "+f"(c[2]), "+f"(c[3])
        : "r"(a[0]), "r"(a[1]), "r"(a[2]), "r"(a[3]), "r"(b0), "r"(b1));
}

template<int K, int NC, bool RELU_IN, bool A_HALF>
__global__ __launch_bounds__(256)
void mma_gemm_kernel(const void* __restrict__ A,
                     const unsigned* __restrict__ Wp,
                     __half* __restrict__ out, int M) {
    constexpr int STRIDE = 20;
    constexpr int WARPS_N = (NC == 128) ? 2 : 1;
    constexpr int WARPS_M = 8 / WARPS_N;
    constexpr int MT = 128 / (WARPS_M * 16);
    constexpr int NSHIFT = (NC == 128) ? 7 : 6;
    constexpr int WWORDS = 16 * NC;

    __shared__ unsigned As[128 * STRIDE];
    __shared__ unsigned Bs[NC * STRIDE];

    int tid = threadIdx.x, wid = tid >> 5, lane = tid & 31;
    int g = lane >> 2, t4 = lane & 3;
    int warp_m = (wid % WARPS_M) * (MT * 16);
    int warp_n = (wid / WARPS_M) * 64;
    int m0 = blockIdx.x * 128;

    float acc[MT][8][4];
#pragma unroll
    for (int mt = 0; mt < MT; mt++)
#pragma unroll
        for (int nt = 0; nt < 8; nt++)
#pragma unroll
            for (int i = 0; i < 4; i++) acc[mt][nt][i] = 0.0f;

    for (int kk = 0; kk < K; kk += 32) {
#pragma unroll
        for (int i = 0; i < 4; i++) {
            int idx = i * 256 + tid;
            int r = idx >> 3, c4 = idx & 7;
            int gm = m0 + r;
            uint2 w = make_uint2(0u, 0u);
            if (gm < M) {
                if (A_HALF) {
                    w = *(const uint2*)((const __half*)A +
                                        (size_t)gm * K + kk + c4 * 4);
                    if (RELU_IN) {
                        __half2 zero = __floats2half2_rn(0.f, 0.f);
                        __half2 a0 = __hmax2(*reinterpret_cast<__half2*>(&w.x), zero);
                        __half2 a1 = __hmax2(*reinterpret_cast<__half2*>(&w.y), zero);
                        w.x = *reinterpret_cast<unsigned*>(&a0);
                        w.y = *reinterpret_cast<unsigned*>(&a1);
                    }
                } else {
                    float4 v = *(const float4*)((const float*)A +
                                                (size_t)gm * K + kk + c4 * 4);
                    if (RELU_IN) {
                        v.x = fmaxf(v.x, 0.f); v.y = fmaxf(v.y, 0.f);
                        v.z = fmaxf(v.z, 0.f); v.w = fmaxf(v.w, 0.f);
                    }
                    __half2 p0 = __floats2half2_rn(v.x, v.y);
                    __half2 p1 = __floats2half2_rn(v.z, v.w);
                    w.x = *reinterpret_cast<unsigned*>(&p0);
                    w.y = *reinterpret_cast<unsigned*>(&p1);
                }
            }
            *(uint2*)&As[r * STRIDE + c4 * 2] = w;
        }
        {
            const unsigned* wp = Wp + (size_t)(kk >> 1) * NC;
#pragma unroll
            for (int i = 0; i < WWORDS / 256; i++) {
                int idx = i * 256 + tid;
                int n = idx & (NC - 1), k2 = idx >> NSHIFT;
                Bs[n * STRIDE + k2] = wp[idx];
            }
        }
        __syncthreads();

#pragma unroll
        for (int ks = 0; ks < 2; ks++) {
            unsigned a[MT][4];
#pragma unroll
            for (int mt = 0; mt < MT; mt++) {
                int r0 = (warp_m + mt * 16 + g) * STRIDE + ks * 8 + t4;
                int r1 = (warp_m + mt * 16 + g + 8) * STRIDE + ks * 8 + t4;
                a[mt][0] = As[r0];     a[mt][1] = As[r1];
                a[mt][2] = As[r0 + 4]; a[mt][3] = As[r1 + 4];
            }
#pragma unroll
            for (int nt = 0; nt < 8; nt++) {
                int bi = (warp_n + nt * 8 + g) * STRIDE + ks * 8 + t4;
                unsigned b0 = Bs[bi], b1 = Bs[bi + 4];
#pragma unroll
                for (int mt = 0; mt < MT; mt++)
                    mma_f16(acc[mt][nt], a[mt], b0, b1);
            }
        }
        __syncthreads();
    }

#pragma unroll
    for (int mt = 0; mt < MT; mt++) {
        int r0 = m0 + warp_m + mt * 16 + g;
        int r1 = r0 + 8;
#pragma unroll
        for (int nt = 0; nt < 8; nt++) {
            int col = warp_n + nt * 8 + t4 * 2;
            if (r0 < M)
                *(__half2*)(out + (size_t)r0 * NC + col) =
                    __floats2half2_rn(acc[mt][nt][0], acc[mt][nt][1]);
            if (r1 < M)
                *(__half2*)(out + (size_t)r1 * NC + col) =
                    __floats2half2_rn(acc[mt][nt][2], acc[mt][nt][3]);
        }
    }
}

// ---------------- fp16 row-gather helper -------------------------------------
__device__ __forceinline__ float4 ld_h4(const __half* __restrict__ row, int lane) {
    uint2 u = __ldg((const uint2*)row + lane);
    float2 fa = __half22float2(*reinterpret_cast<__half2*>(&u.x));
    float2 fb = __half22float2(*reinterpret_cast<__half2*>(&u.y));
    return make_float4(fa.x, fa.y, fb.x, fb.y);
}

// ---------------- CSR aggregation: layer 1 (warp per node, node range) ------
__global__ __launch_bounds__(256)
void agg1_kernel(const float* __restrict__ b1, int n0, int n1) {
    int node = n0 + ((blockIdx.x * blockDim.x + threadIdx.x) >> 5);
    int lane = threadIdx.x & 31;
    if (node >= n1) return;
    int beg = g_rowstart[node];
    int cnt = g_cnt[node];

    float4 acc = make_float4(0.f, 0.f, 0.f, 0.f);
    int j = 0;
    for (; j + 1 < cnt; j += 2) {
        int2 e0 = __ldg(&g_csr[beg + j]);
        int2 e1 = __ldg(&g_csr[beg + j + 1]);
        float w0 = __int_as_float(e0.y);
        float w1 = __int_as_float(e1.y);
        float4 v0 = ld_h4(g_h1h + (size_t)e0.x * HID_CH, lane);
        float4 v1 = ld_h4(g_h1h + (size_t)e1.x * HID_CH, lane);
        acc.x += w0 * v0.x + w1 * v1.x;
        acc.y += w0 * v0.y + w1 * v1.y;
        acc.z += w0 * v0.z + w1 * v1.z;
        acc.w += w0 * v0.w + w1 * v1.w;
    }
    if (j < cnt) {
        int2 e = __ldg(&g_csr[beg + j]);
        float w = __int_as_float(e.y);
        float4 v = ld_h4(g_h1h + (size_t)e.x * HID_CH, lane);
        acc.x += w * v.x; acc.y += w * v.y;
        acc.z += w * v.z; acc.w += w * v.w;
    }
    float di = g_dinv[node];
    float sw = di * di;
    float4 h = ld_h4(g_h1h + (size_t)node * HID_CH, lane);
    float4 b = ((const float4*)b1)[lane];
    acc.x += b.x + sw * h.x;
    acc.y += b.y + sw * h.y;
    acc.z += b.z + sw * h.z;
    acc.w += b.w + sw * h.w;
    __half2 p0 = __floats2half2_rn(acc.x, acc.y);
    __half2 p1 = __floats2half2_rn(acc.z, acc.w);
    uint2 u;
    u.x = *reinterpret_cast<unsigned*>(&p0);
    u.y = *reinterpret_cast<unsigned*>(&p1);
    ((uint2*)(g_a1h + (size_t)node * HID_CH))[lane] = u;
}

// ---------------- CSR aggregation: layer 2 (16 lanes per node) --------------
__global__ __launch_bounds__(256)
void agg2_kernel(const float* __restrict__ b2, float* __restrict__ out) {
    int node = (blockIdx.x * blockDim.x + threadIdx.x) >> 4;
    int lane = threadIdx.x & 15;
    if (node >= N_NODES) return;
    int beg = g_rowstart[node];
    int cnt = g_cnt[node];

    float4 acc = make_float4(0.f, 0.f, 0.f, 0.f);
    int j = 0;
    for (; j + 1 < cnt; j += 2) {
        int2 e0 = __ldg(&g_csr[beg + j]);
        int2 e1 = __ldg(&g_csr[beg + j + 1]);
        float w0 = __int_as_float(e0.y);
        float w1 = __int_as_float(e1.y);
        float4 v0 = ld_h4(g_h2h + (size_t)e0.x * OUT_CH, lane);
        float4 v1 = ld_h4(g_h2h + (size_t)e1.x * OUT_CH, lane);
        acc.x += w0 * v0.x + w1 * v1.x;
        acc.y += w0 * v0.y + w1 * v1.y;
        acc.z += w0 * v0.z + w1 * v1.z;
        acc.w += w0 * v0.w + w1 * v1.w;
    }
    if (j < cnt) {
        int2 e = __ldg(&g_csr[beg + j]);
        float w = __int_as_float(e.y);
        float4 v = ld_h4(g_h2h + (size_t)e.x * OUT_CH, lane);
        acc.x += w * v.x; acc.y += w * v.y;
        acc.z += w * v.z; acc.w += w * v.w;
    }
    float di = g_dinv[node];
    float sw = di * di;
    float4 h = ld_h4(g_h2h + (size_t)node * OUT_CH, lane);
    float4 b = ((const float4*)b2)[lane];
    acc.x += b.x + sw * h.x;
    acc.y += b.y + sw * h.y;
    acc.z += b.z + sw * h.z;
    acc.w += b.w + sw * h.w;
    ((float4*)(out + (size_t)node * OUT_CH))[lane] = acc;
}

// ---------------- launch ----------------------------------------------------
extern "C" void kernel_launch(void* const* d_in, const int* in_sizes, int n_in,
                              void* d_out, int out_size) {
    const float* x  = (const float*)d_in[0];
    const void*  ei = d_in[1];
    const float* W1 = (const float*)d_in[2];
    const float* b1 = (const float*)d_in[3];
    const float* W2 = (const float*)d_in[4];
    const float* b2 = (const float*)d_in[5];
    float* out = (float*)d_out;

    __half *p_h1h, *p_a1h, *p_h2h;
    unsigned *p_W1p, *p_W2p;
    cudaGetSymbolAddress((void**)&p_h1h, g_h1h);
    cudaGetSymbolAddress((void**)&p_a1h, g_a1h);
    cudaGetSymbolAddress((void**)&p_h2h, g_h2h);
    cudaGetSymbolAddress((void**)&p_W1p, g_W1p);
    cudaGetSymbolAddress((void**)&p_W2p, g_W2p);

    static cudaStream_t s_side = nullptr;
    static cudaEvent_t  s_fork = nullptr, s_join = nullptr;
    static cudaEvent_t  s_fork2 = nullptr, s_join2 = nullptr;
    if (s_side == nullptr) {
        cudaStreamCreateWithFlags(&s_side, cudaStreamNonBlocking);
        cudaEventCreateWithFlags(&s_fork,  cudaEventDisableTiming);
        cudaEventCreateWithFlags(&s_join,  cudaEventDisableTiming);
        cudaEventCreateWithFlags(&s_fork2, cudaEventDisableTiming);
        cudaEventCreateWithFlags(&s_join2, cudaEventDisableTiming);
    }

    // ---- fork: CSR-build branch concurrent with wpack + GEMM1 ----
    cudaEventRecord(s_fork, 0);
    cudaStreamWaitEvent(s_side, s_fork, 0);

    // side branch: edge prep -> CSR
    zero_detect_kernel<<<NB_SCAN, 256, 0, s_side>>>((const unsigned*)ei);
    count_deg_kernel<<<(N_EDGES / 4 + 255) / 256, 256, 0, s_side>>>(ei);
    scan1_kernel<<<NB_SCAN, 256, 0, s_side>>>();
    scan23_kernel<<<NB_SCAN, 256, 0, s_side>>>();
    fill_csr_kernel<<<(N_EDGES / 2 + 255) / 256, 256, 0, s_side>>>(ei);
    cudaEventRecord(s_join, s_side);

    // main branch: W pack + GEMM1
    wpack_kernel<<<((IN_CH / 2) * HID_CH + 255) / 256, 256>>>(W1, W2);
    mma_gemm_kernel<IN_CH, HID_CH, false, false>
        <<<(N_NODES + 127) / 128, 256>>>(x, p_W1p, p_h1h, N_NODES);

    // join: aggregation needs both CSR and h1
    cudaStreamWaitEvent(0, s_join, 0);

    // ---- pipelined tail: agg1 halves overlap GEMM2 first half ----
    cudaEventRecord(s_fork2, 0);
    cudaStreamWaitEvent(s_side, s_fork2, 0);

    // half A (nodes [0, HALF_N)) on main
    agg1_kernel<<<(HALF_N * 32 + 255) / 256, 256>>>(b1, 0, HALF_N);
    // half B on side, concurrent with GEMM2_A
    agg1_kernel<<<((N_NODES - HALF_N) * 32 + 255) / 256, 256, 0, s_side>>>
        (b1, HALF_N, N_NODES);
    cudaEventRecord(s_join2, s_side);

    // GEMM2 on rows [0, HALF_N) while agg1_B runs
    mma_gemm_kernel<HID_CH, OUT_CH, true, true>
        <<<(HALF_N + 127) / 128, 256>>>(p_a1h, p_W2p, p_h2h, HALF_N);

    cudaStreamWaitEvent(0, s_join2, 0);
    // GEMM2 on rows [HALF_N, N_NODES)
    mma_gemm_kernel<HID_CH, OUT_CH, true, true>
        <<<(N_NODES - HALF_N + 127) / 128, 256>>>(
            p_a1h + (size_t)HALF_N * HID_CH, p_W2p,
            p_h2h + (size_t)HALF_N * OUT_CH, N_NODES - HALF_N);

    agg2_kernel<<<(N_NODES * 16 + 255) / 256, 256>>>(b2, out);
}

// round 10
// speedup vs baseline: 2.8202x; 1.0037x over previous
#include <cuda_runtime.h>
#include <cuda_fp16.h>

#define N_NODES 100000
#define N_EDGES 1600000
#define IN_CH   256
#define HID_CH  128
#define OUT_CH  64
#define NB_SCAN ((N_NODES + 255) / 256)   // 391

// ---------------- scratch (device globals; no cudaMalloc allowed) ----------
__device__ int      g_cnt     [N_NODES];
__device__ int      g_rowstart[N_NODES];
__device__ int      g_cursor  [N_NODES];
__device__ int      g_part    [512];
__device__ int2     g_csr     [N_EDGES];          // (src, weight-as-int)
__device__ float    g_dinv    [N_NODES];
__device__ __half   g_h1h[(size_t)N_NODES * HID_CH];   // x @ W1   (fp16)
__device__ __half   g_h2h[(size_t)N_NODES * OUT_CH];   // relu(a1) @ W2 (fp16)
__device__ unsigned g_W1p[(IN_CH / 2) * HID_CH];   // fp16 packed, 2 k per word
__device__ unsigned g_W2p[(HID_CH / 2) * OUT_CH];
__device__ int      g_is64;

// ---------------- prep: zero counters + dtype detect ------------------------
__global__ void zero_detect_kernel(const unsigned* __restrict__ w) {
    int n = blockIdx.x * blockDim.x + threadIdx.x;
    if (n < N_NODES) g_cnt[n] = 0;
    if (n == 0) {
        int is64 = 1;
        for (int i = 0; i < 64; i++)
            if (w[2 * i + 1] != 0u) { is64 = 0; break; }
        g_is64 = is64;
    }
}

// 4 edges per thread
__global__ void count_deg_kernel(const void* __restrict__ ei) {
    int t = blockIdx.x * blockDim.x + threadIdx.x;
    if (t >= N_EDGES / 4) return;
    int d0, d1, d2, d3;
    if (g_is64) {
        const longlong2* p =
            (const longlong2*)((const long long*)ei + N_EDGES);
        longlong2 a = p[2 * t], b = p[2 * t + 1];
        d0 = (int)a.x; d1 = (int)a.y; d2 = (int)b.x; d3 = (int)b.y;
    } else {
        const int4* p = (const int4*)((const int*)ei + N_EDGES);
        int4 a = p[t];
        d0 = a.x; d1 = a.y; d2 = a.z; d3 = a.w;
    }
    atomicAdd(&g_cnt[d0], 1);
    atomicAdd(&g_cnt[d1], 1);
    atomicAdd(&g_cnt[d2], 1);
    atomicAdd(&g_cnt[d3], 1);
}

// ---------------- W pack (fp16, 2 k per word, n-fastest source) -------------
__global__ void wpack_kernel(const float* __restrict__ W1,
                             const float* __restrict__ W2) {
    int i = blockIdx.x * blockDim.x + threadIdx.x;
    if (i < (IN_CH / 2) * HID_CH) {
        int k2 = i / HID_CH, n = i % HID_CH;
        float w0 = W1[(size_t)(2 * k2) * HID_CH + n];
        float w1 = W1[(size_t)(2 * k2 + 1) * HID_CH + n];
        __half2 p = __floats2half2_rn(w0, w1);
        g_W1p[i] = *reinterpret_cast<unsigned*>(&p);
    }
    if (i < (HID_CH / 2) * OUT_CH) {
        int k2 = i / OUT_CH, n = i % OUT_CH;
        float w0 = W2[(size_t)(2 * k2) * OUT_CH + n];
        float w1 = W2[(size_t)(2 * k2 + 1) * OUT_CH + n];
        __half2 p = __floats2half2_rn(w0, w1);
        g_W2p[i] = *reinterpret_cast<unsigned*>(&p);
    }
}

// ---------------- scans (dinv fused into scan1; scan2 fused into scan23) ----
__global__ void scan1_kernel() {
    __shared__ int sm[256];
    int tid = threadIdx.x;
    int i = blockIdx.x * 256 + tid;
    int v = (i < N_NODES) ? g_cnt[i] : 0;
    if (i < N_NODES) g_dinv[i] = rsqrtf((float)(v + 1));   // +1 self-loop
    sm[tid] = v;
    __syncthreads();
#pragma unroll
    for (int off = 1; off < 256; off <<= 1) {
        int t = (tid >= off) ? sm[tid - off] : 0;
        __syncthreads();
        sm[tid] += t;
        __syncthreads();
    }
    if (i < N_NODES) g_rowstart[i] = sm[tid] - v;
    if (tid == 255) g_part[blockIdx.x] = sm[tid];
}

__global__ void scan23_kernel() {
    __shared__ int sm[256];
    int tid = threadIdx.x;
    int v = 0;
    for (int i = tid; i < blockIdx.x; i += 256) v += g_part[i];
    sm[tid] = v;
    __syncthreads();
#pragma unroll
    for (int off = 128; off > 0; off >>= 1) {
        if (tid < off) sm[tid] += sm[tid + off];
        __syncthreads();
    }
    int base = sm[0];
    int i = blockIdx.x * 256 + tid;
    if (i < N_NODES) {
        int r = g_rowstart[i] + base;
        g_rowstart[i] = r;
        g_cursor[i] = r;
    }
}

// ---------------- CSR fill (2 edges per thread) ------------------------------
__global__ void fill_csr_kernel(const void* __restrict__ ei) {
    int t = blockIdx.x * blockDim.x + threadIdx.x;
    if (t >= N_EDGES / 2) return;
    int s0, d0, s1, d1;
    if (g_is64) {
        const longlong2* ps = (const longlong2*)ei;
        const longlong2* pd = (const longlong2*)((const long long*)ei + N_EDGES);
        longlong2 a = ps[t], b = pd[t];
        s0 = (int)a.x; s1 = (int)a.y;
        d0 = (int)b.x; d1 = (int)b.y;
    } else {
        const int2* ps = (const int2*)ei;
        const int2* pd = (const int2*)((const int*)ei + N_EDGES);
        int2 a = ps[t], b = pd[t];
        s0 = a.x; s1 = a.y;
        d0 = b.x; d1 = b.y;
    }
    float w0 = g_dinv[s0] * g_dinv[d0];
    float w1 = g_dinv[s1] * g_dinv[d1];
    int slot0 = atomicAdd(&g_cursor[d0], 1);
    g_csr[slot0] = make_int2(s0, __float_as_int(w0));
    int slot1 = atomicAdd(&g_cursor[d1], 1);
    g_csr[slot1] = make_int2(s1, __float_as_int(w1));
}

// ---------------- tensor-core mma helper -------------------------------------
__device__ __forceinline__ void mma_f16(float* c, const unsigned* a,
                                        unsigned b0, unsigned b1) {
    asm volatile(
        "mma.sync.aligned.m16n8k16.row.col.f32.f16.f16.f32 "
        "{%0,%1,%2,%3},{%4,%5,%6,%7},{%8,%9},{%0,%1,%2,%3};"
        : "+f"(c[0]), "+f"(c[1]), "+f"(c[2]), "+f"(c[3])
        : "r"(a[0]), "r"(a[1]), "r"(a[2]), "r"(a[3]), "r"(b0), "r"(b1));
}

// ---------------- GEMM1: h1(fp16) = x(fp32) @ W1 -----------------------------
__global__ __launch_bounds__(256)
void gemm1_kernel(const float* __restrict__ A,
                  const unsigned* __restrict__ Wp,
                  __half* __restrict__ out, int M) {
    constexpr int K = IN_CH, NC = HID_CH;
    constexpr int STRIDE = 20;
    constexpr int WARPS_M = 4;      // WARPS_N = 2
    constexpr int MT = 2;

    __shared__ unsigned As[128 * STRIDE];
    __shared__ unsigned Bs[NC * STRIDE];

    int tid = threadIdx.x, wid = tid >> 5, lane = tid & 31;
    int g = lane >> 2, t4 = lane & 3;
    int warp_m = (wid % WARPS_M) * (MT * 16);
    int warp_n = (wid / WARPS_M) * 64;
    int m0 = blockIdx.x * 128;

    float acc[MT][8][4];
#pragma unroll
    for (int mt = 0; mt < MT; mt++)
#pragma unroll
        for (int nt = 0; nt < 8; nt++)
#pragma unroll
            for (int i = 0; i < 4; i++) acc[mt][nt][i] = 0.0f;

    for (int kk = 0; kk < K; kk += 32) {
#pragma unroll
        for (int i = 0; i < 4; i++) {
            int idx = i * 256 + tid;
            int r = idx >> 3, c4 = idx & 7;
            int gm = m0 + r;
            uint2 w = make_uint2(0u, 0u);
            if (gm < M) {
                float4 v = *(const float4*)(A + (size_t)gm * K + kk + c4 * 4);
                __half2 p0 = __floats2half2_rn(v.x, v.y);
                __half2 p1 = __floats2half2_rn(v.z, v.w);
                w.x = *reinterpret_cast<unsigned*>(&p0);
                w.y = *reinterpret_cast<unsigned*>(&p1);
            }
            *(uint2*)&As[r * STRIDE + c4 * 2] = w;
        }
        {
            // B chunk: (32/2) * 128 = 2048 packed words -> 8 x 256
            const unsigned* wp = Wp + (size_t)(kk >> 1) * NC;
#pragma unroll
            for (int i = 0; i < 8; i++) {
                int idx = i * 256 + tid;
                int n = idx & 127, k2 = idx >> 7;
                Bs[n * STRIDE + k2] = wp[idx];
            }
        }
        __syncthreads();

#pragma unroll
        for (int ks = 0; ks < 2; ks++) {
            unsigned a[MT][4];
#pragma unroll
            for (int mt = 0; mt < MT; mt++) {
                int r0 = (warp_m + mt * 16 + g) * STRIDE + ks * 8 + t4;
                int r1 = (warp_m + mt * 16 + g + 8) * STRIDE + ks * 8 + t4;
                a[mt][0] = As[r0];     a[mt][1] = As[r1];
                a[mt][2] = As[r0 + 4]; a[mt][3] = As[r1 + 4];
            }
#pragma unroll
            for (int nt = 0; nt < 8; nt++) {
                int bi = (warp_n + nt * 8 + g) * STRIDE + ks * 8 + t4;
                unsigned b0 = Bs[bi], b1 = Bs[bi + 4];
#pragma unroll
                for (int mt = 0; mt < MT; mt++)
                    mma_f16(acc[mt][nt], a[mt], b0, b1);
            }
        }
        __syncthreads();
    }

#pragma unroll
    for (int mt = 0; mt < MT; mt++) {
        int r0 = m0 + warp_m + mt * 16 + g;
        int r1 = r0 + 8;
#pragma unroll
        for (int nt = 0; nt < 8; nt++) {
            int col = warp_n + nt * 8 + t4 * 2;
            if (r0 < M)
                *(__half2*)(out + (size_t)r0 * NC + col) =
                    __floats2half2_rn(acc[mt][nt][0], acc[mt][nt][1]);
            if (r1 < M)
                *(__half2*)(out + (size_t)r1 * NC + col) =
                    __floats2half2_rn(acc[mt][nt][2], acc[mt][nt][3]);
        }
    }
}

// ---------------- fp16 row-gather helper -------------------------------------
__device__ __forceinline__ float4 ld_h4(const __half* __restrict__ row, int lane) {
    uint2 u = __ldg((const uint2*)row + lane);
    float2 fa = __half22float2(*reinterpret_cast<__half2*>(&u.x));
    float2 fb = __half22float2(*reinterpret_cast<__half2*>(&u.y));
    return make_float4(fa.x, fa.y, fb.x, fb.y);
}

// ---------------- FUSED: agg1 (CSR) + relu + GEMM2 --------------------------
// Block handles 128 nodes: aggregate a1 rows straight into the GEMM smem
// A-tile (fp16, STRIDE-20 fragment layout), then mma against W2.
__global__ __launch_bounds__(256)
void agg1_gemm2_kernel(const float* __restrict__ b1,
                       const unsigned* __restrict__ Wp,
                       __half* __restrict__ out, int M) {
    constexpr int STRIDE = 20;
    constexpr int NC = OUT_CH;      // 64

    __shared__ unsigned As[4][128 * STRIDE];   // 4 k-chunks of 32
    __shared__ unsigned Bs[NC * STRIDE];

    int tid = threadIdx.x, wid = tid >> 5, lane = tid & 31;
    int g = lane >> 2, t4 = lane & 3;
    int m0 = blockIdx.x * 128;

    // ---- phase 1: aggregation, warp w handles rows w*16 .. w*16+15 ----
    float4 bias = ((const float4*)b1)[lane];
    int chunk = lane >> 3;
    int wslot = (lane & 7) * 2;
#pragma unroll 1
    for (int i = 0; i < 16; i++) {
        int r = wid * 16 + i;
        int node = m0 + r;
        uint2 u = make_uint2(0u, 0u);
        if (node < M) {
            int beg = g_rowstart[node];
            int cnt = g_cnt[node];
            float4 acc = make_float4(0.f, 0.f, 0.f, 0.f);
            int j = 0;
            for (; j + 3 < cnt; j += 4) {
                int2 e0 = __ldg(&g_csr[beg + j]);
                int2 e1 = __ldg(&g_csr[beg + j + 1]);
                int2 e2 = __ldg(&g_csr[beg + j + 2]);
                int2 e3 = __ldg(&g_csr[beg + j + 3]);
                float4 v0 = ld_h4(g_h1h + (size_t)e0.x * HID_CH, lane);
                float4 v1 = ld_h4(g_h1h + (size_t)e1.x * HID_CH, lane);
                float4 v2 = ld_h4(g_h1h + (size_t)e2.x * HID_CH, lane);
                float4 v3 = ld_h4(g_h1h + (size_t)e3.x * HID_CH, lane);
                float w0 = __int_as_float(e0.y), w1 = __int_as_float(e1.y);
                float w2 = __int_as_float(e2.y), w3 = __int_as_float(e3.y);
                acc.x += w0 * v0.x + w1 * v1.x + w2 * v2.x + w3 * v3.x;
                acc.y += w0 * v0.y + w1 * v1.y + w2 * v2.y + w3 * v3.y;
                acc.z += w0 * v0.z + w1 * v1.z + w2 * v2.z + w3 * v3.z;
                acc.w += w0 * v0.w + w1 * v1.w + w2 * v2.w + w3 * v3.w;
            }
            for (; j < cnt; j++) {
                int2 e = __ldg(&g_csr[beg + j]);
                float w = __int_as_float(e.y);
                float4 v = ld_h4(g_h1h + (size_t)e.x * HID_CH, lane);
                acc.x += w * v.x; acc.y += w * v.y;
                acc.z += w * v.z; acc.w += w * v.w;
            }
            float di = g_dinv[node];
            float sw = di * di;
            float4 h = ld_h4(g_h1h + (size_t)node * HID_CH, lane);
            acc.x = fmaxf(bias.x + acc.x + sw * h.x, 0.f);   // +bias, relu
            acc.y = fmaxf(bias.y + acc.y + sw * h.y, 0.f);
            acc.z = fmaxf(bias.z + acc.z + sw * h.z, 0.f);
            acc.w = fmaxf(bias.w + acc.w + sw * h.w, 0.f);
            __half2 p0 = __floats2half2_rn(acc.x, acc.y);
            __half2 p1 = __floats2half2_rn(acc.z, acc.w);
            u.x = *reinterpret_cast<unsigned*>(&p0);
            u.y = *reinterpret_cast<unsigned*>(&p1);
        }
        *(uint2*)&As[chunk][r * STRIDE + wslot] = u;
    }
    __syncthreads();

    // ---- phase 2: GEMM vs W2 (K=128, NC=64; 8 warps over M) ----
    int warp_m = wid * 16;
    float acc[8][4];
#pragma unroll
    for (int nt = 0; nt < 8; nt++)
#pragma unroll
        for (int i = 0; i < 4; i++) acc[nt][i] = 0.0f;

#pragma unroll
    for (int c = 0; c < 4; c++) {
        {
            // B chunk: (32/2) * 64 = 1024 packed words -> 4 x 256
            const unsigned* wp = Wp + (size_t)(c * 16) * NC;
#pragma unroll
            for (int i = 0; i < 4; i++) {
                int idx = i * 256 + tid;
                int n = idx & 63, k2 = idx >> 6;
                Bs[n * STRIDE + k2] = wp[idx];
            }
        }
        __syncthreads();

#pragma unroll
        for (int ks = 0; ks < 2; ks++) {
            unsigned a[4];
            int r0 = (warp_m + g) * STRIDE + ks * 8 + t4;
            int r1 = (warp_m + g + 8) * STRIDE + ks * 8 + t4;
            a[0] = As[c][r0];     a[1] = As[c][r1];
            a[2] = As[c][r0 + 4]; a[3] = As[c][r1 + 4];
#pragma unroll
            for (int nt = 0; nt < 8; nt++) {
                int bi = (nt * 8 + g) * STRIDE + ks * 8 + t4;
                unsigned b0 = Bs[bi], b1 = Bs[bi + 4];
                mma_f16(acc[nt], a, b0, b1);
            }
        }
        __syncthreads();
    }

    // ---- epilogue: h2 fp16 ----
    int r0 = m0 + warp_m + g;
    int r1 = r0 + 8;
#pragma unroll
    for (int nt = 0; nt < 8; nt++) {
        int col = nt * 8 + t4 * 2;
        if (r0 < M)
            *(__half2*)(out + (size_t)r0 * NC + col) =
                __floats2half2_rn(acc[nt][0], acc[nt][1]);
        if (r1 < M)
            *(__half2*)(out + (size_t)r1 * NC + col) =
                __floats2half2_rn(acc[nt][2], acc[nt][3]);
    }
}

// ---------------- CSR aggregation: layer 2 (16 lanes per node) --------------
__global__ __launch_bounds__(256)
void agg2_kernel(const float* __restrict__ b2, float* __restrict__ out) {
    int node = (blockIdx.x * blockDim.x + threadIdx.x) >> 4;
    int lane = threadIdx.x & 15;
    if (node >= N_NODES) return;
    int beg = g_rowstart[node];
    int cnt = g_cnt[node];

    float4 acc = make_float4(0.f, 0.f, 0.f, 0.f);
    int j = 0;
    for (; j + 3 < cnt; j += 4) {
        int2 e0 = __ldg(&g_csr[beg + j]);
        int2 e1 = __ldg(&g_csr[beg + j + 1]);
        int2 e2 = __ldg(&g_csr[beg + j + 2]);
        int2 e3 = __ldg(&g_csr[beg + j + 3]);
        float4 v0 = ld_h4(g_h2h + (size_t)e0.x * OUT_CH, lane);
        float4 v1 = ld_h4(g_h2h + (size_t)e1.x * OUT_CH, lane);
        float4 v2 = ld_h4(g_h2h + (size_t)e2.x * OUT_CH, lane);
        float4 v3 = ld_h4(g_h2h + (size_t)e3.x * OUT_CH, lane);
        float w0 = __int_as_float(e0.y), w1 = __int_as_float(e1.y);
        float w2 = __int_as_float(e2.y), w3 = __int_as_float(e3.y);
        acc.x += w0 * v0.x + w1 * v1.x + w2 * v2.x + w3 * v3.x;
        acc.y += w0 * v0.y + w1 * v1.y + w2 * v2.y + w3 * v3.y;
        acc.z += w0 * v0.z + w1 * v1.z + w2 * v2.z + w3 * v3.z;
        acc.w += w0 * v0.w + w1 * v1.w + w2 * v2.w + w3 * v3.w;
    }
    for (; j < cnt; j++) {
        int2 e = __ldg(&g_csr[beg + j]);
        float w = __int_as_float(e.y);
        float4 v = ld_h4(g_h2h + (size_t)e.x * OUT_CH, lane);
        acc.x += w * v.x; acc.y += w * v.y;
        acc.z += w * v.z; acc.w += w * v.w;
    }
    float di = g_dinv[node];
    float sw = di * di;
    float4 h = ld_h4(g_h2h + (size_t)node * OUT_CH, lane);
    float4 b = ((const float4*)b2)[lane];
    acc.x += b.x + sw * h.x;
    acc.y += b.y + sw * h.y;
    acc.z += b.z + sw * h.z;
    acc.w += b.w + sw * h.w;
    ((float4*)(out + (size_t)node * OUT_CH))[lane] = acc;
}

// ---------------- launch ----------------------------------------------------
extern "C" void kernel_launch(void* const* d_in, const int* in_sizes, int n_in,
                              void* d_out, int out_size) {
    const float* x  = (const float*)d_in[0];
    const void*  ei = d_in[1];
    const float* W1 = (const float*)d_in[2];
    const float* b1 = (const float*)d_in[3];
    const float* W2 = (const float*)d_in[4];
    const float* b2 = (const float*)d_in[5];
    float* out = (float*)d_out;

    __half *p_h1h, *p_h2h;
    unsigned *p_W1p, *p_W2p;
    cudaGetSymbolAddress((void**)&p_h1h, g_h1h);
    cudaGetSymbolAddress((void**)&p_h2h, g_h2h);
    cudaGetSymbolAddress((void**)&p_W1p, g_W1p);
    cudaGetSymbolAddress((void**)&p_W2p, g_W2p);

    static cudaStream_t s_side = nullptr;
    static cudaEvent_t  s_fork = nullptr, s_join = nullptr;
    if (s_side == nullptr) {
        cudaStreamCreateWithFlags(&s_side, cudaStreamNonBlocking);
        cudaEventCreateWithFlags(&s_fork, cudaEventDisableTiming);
        cudaEventCreateWithFlags(&s_join, cudaEventDisableTiming);
    }

    // ---- fork: CSR-build branch concurrent with wpack + GEMM1 ----
    cudaEventRecord(s_fork, 0);
    cudaStreamWaitEvent(s_side, s_fork, 0);

    zero_detect_kernel<<<NB_SCAN, 256, 0, s_side>>>((const unsigned*)ei);
    count_deg_kernel<<<(N_EDGES / 4 + 255) / 256, 256, 0, s_side>>>(ei);
    scan1_kernel<<<NB_SCAN, 256, 0, s_side>>>();
    scan23_kernel<<<NB_SCAN, 256, 0, s_side>>>();
    fill_csr_kernel<<<(N_EDGES / 2 + 255) / 256, 256, 0, s_side>>>(ei);
    cudaEventRecord(s_join, s_side);

    wpack_kernel<<<((IN_CH / 2) * HID_CH + 255) / 256, 256>>>(W1, W2);
    gemm1_kernel<<<(N_NODES + 127) / 128, 256>>>(x, p_W1p, p_h1h, N_NODES);

    cudaStreamWaitEvent(0, s_join, 0);

    // fused agg1 + relu + GEMM2 -> h2
    agg1_gemm2_kernel<<<(N_NODES + 127) / 128, 256>>>(b1, p_W2p, p_h2h, N_NODES);
    // final aggregation -> out
    agg2_kernel<<<(N_NODES * 16 + 255) / 256, 256>>>(b2, out);
}

// round 11
// speedup vs baseline: 3.0588x; 1.0846x over previous
#include <cuda_runtime.h>
#include <cuda_fp16.h>

#define N_NODES 100000
#define N_EDGES 1600000
#define IN_CH   256
#define HID_CH  128
#define OUT_CH  64
#define NB_SCAN ((N_NODES + 255) / 256)   // 391

// ---------------- scratch (device globals; no cudaMalloc allowed) ----------
__device__ int      g_cnt     [N_NODES];
__device__ int      g_rowstart[N_NODES];
__device__ int      g_cursor  [N_NODES];
__device__ int      g_part    [512];
__device__ int2     g_csr     [N_EDGES];          // (src, weight-as-int)
__device__ float    g_dinv    [N_NODES];
__device__ __half   g_h1h[(size_t)N_NODES * HID_CH];   // x @ W1   (fp16)
__device__ __half   g_h2h[(size_t)N_NODES * OUT_CH];   // relu(a1) @ W2 (fp16)
__device__ unsigned g_W1p[(IN_CH / 2) * HID_CH];   // fp16 packed, 2 k per word
__device__ unsigned g_W2p[(HID_CH / 2) * OUT_CH];
__device__ int      g_is64;

// ---------------- prep: zero counters + dtype detect ------------------------
__global__ void zero_detect_kernel(const unsigned* __restrict__ w) {
    int n = blockIdx.x * blockDim.x + threadIdx.x;
    if (n < N_NODES) g_cnt[n] = 0;
    if (n == 0) {
        int is64 = 1;
        for (int i = 0; i < 64; i++)
            if (w[2 * i + 1] != 0u) { is64 = 0; break; }
        g_is64 = is64;
    }
}

// 4 edges per thread
__global__ void count_deg_kernel(const void* __restrict__ ei) {
    int t = blockIdx.x * blockDim.x + threadIdx.x;
    if (t >= N_EDGES / 4) return;
    int d0, d1, d2, d3;
    if (g_is64) {
        const longlong2* p =
            (const longlong2*)((const long long*)ei + N_EDGES);
        longlong2 a = p[2 * t], b = p[2 * t + 1];
        d0 = (int)a.x; d1 = (int)a.y; d2 = (int)b.x; d3 = (int)b.y;
    } else {
        const int4* p = (const int4*)((const int*)ei + N_EDGES);
        int4 a = p[t];
        d0 = a.x; d1 = a.y; d2 = a.z; d3 = a.w;
    }
    atomicAdd(&g_cnt[d0], 1);
    atomicAdd(&g_cnt[d1], 1);
    atomicAdd(&g_cnt[d2], 1);
    atomicAdd(&g_cnt[d3], 1);
}

// ---------------- W pack (fp16, 2 k per word, n-fastest source) -------------
__global__ void wpack_kernel(const float* __restrict__ W1,
                             const float* __restrict__ W2) {
    int i = blockIdx.x * blockDim.x + threadIdx.x;
    if (i < (IN_CH / 2) * HID_CH) {
        int k2 = i / HID_CH, n = i % HID_CH;
        float w0 = W1[(size_t)(2 * k2) * HID_CH + n];
        float w1 = W1[(size_t)(2 * k2 + 1) * HID_CH + n];
        __half2 p = __floats2half2_rn(w0, w1);
        g_W1p[i] = *reinterpret_cast<unsigned*>(&p);
    }
    if (i < (HID_CH / 2) * OUT_CH) {
        int k2 = i / OUT_CH, n = i % OUT_CH;
        float w0 = W2[(size_t)(2 * k2) * OUT_CH + n];
        float w1 = W2[(size_t)(2 * k2 + 1) * OUT_CH + n];
        __half2 p = __floats2half2_rn(w0, w1);
        g_W2p[i] = *reinterpret_cast<unsigned*>(&p);
    }
}

// ---------------- scans (dinv fused into scan1; scan2 fused into scan23) ----
__global__ void scan1_kernel() {
    __shared__ int sm[256];
    int tid = threadIdx.x;
    int i = blockIdx.x * 256 + tid;
    int v = (i < N_NODES) ? g_cnt[i] : 0;
    if (i < N_NODES) g_dinv[i] = rsqrtf((float)(v + 1));   // +1 self-loop
    sm[tid] = v;
    __syncthreads();
#pragma unroll
    for (int off = 1; off < 256; off <<= 1) {
        int t = (tid >= off) ? sm[tid - off] : 0;
        __syncthreads();
        sm[tid] += t;
        __syncthreads();
    }
    if (i < N_NODES) g_rowstart[i] = sm[tid] - v;
    if (tid == 255) g_part[blockIdx.x] = sm[tid];
}

__global__ void scan23_kernel() {
    __shared__ int sm[256];
    int tid = threadIdx.x;
    int v = 0;
    for (int i = tid; i < blockIdx.x; i += 256) v += g_part[i];
    sm[tid] = v;
    __syncthreads();
#pragma unroll
    for (int off = 128; off > 0; off >>= 1) {
        if (tid < off) sm[tid] += sm[tid + off];
        __syncthreads();
    }
    int base = sm[0];
    int i = blockIdx.x * 256 + tid;
    if (i < N_NODES) {
        int r = g_rowstart[i] + base;
        g_rowstart[i] = r;
        g_cursor[i] = r;
    }
}

// ---------------- CSR fill (2 edges per thread) ------------------------------
__global__ void fill_csr_kernel(const void* __restrict__ ei) {
    int t = blockIdx.x * blockDim.x + threadIdx.x;
    if (t >= N_EDGES / 2) return;
    int s0, d0, s1, d1;
    if (g_is64) {
        const longlong2* ps = (const longlong2*)ei;
        const longlong2* pd = (const longlong2*)((const long long*)ei + N_EDGES);
        longlong2 a = ps[t], b = pd[t];
        s0 = (int)a.x; s1 = (int)a.y;
        d0 = (int)b.x; d1 = (int)b.y;
    } else {
        const int2* ps = (const int2*)ei;
        const int2* pd = (const int2*)((const int*)ei + N_EDGES);
        int2 a = ps[t], b = pd[t];
        s0 = a.x; s1 = a.y;
        d0 = b.x; d1 = b.y;
    }
    float w0 = g_dinv[s0] * g_dinv[d0];
    float w1 = g_dinv[s1] * g_dinv[d1];
    int slot0 = atomicAdd(&g_cursor[d0], 1);
    g_csr[slot0] = make_int2(s0, __float_as_int(w0));
    int slot1 = atomicAdd(&g_cursor[d1], 1);
    g_csr[slot1] = make_int2(s1, __float_as_int(w1));
}

// ---------------- tensor-core mma helper -------------------------------------
__device__ __forceinline__ void mma_f16(float* c, const unsigned* a,
                                        unsigned b0, unsigned b1) {
    asm volatile(
        "mma.sync.aligned.m16n8k16.row.col.f32.f16.f16.f32 "
        "{%0,%1,%2,%3},{%4,%5,%6,%7},{%8,%9},{%0,%1,%2,%3};"
        : "+f"(c[0]), "+f"(c[1]), "+f"(c[2]), "+f"(c[3])
        : "r"(a[0]), "r"(a[1]), "r"(a[2]), "r"(a[3]), "r"(b0), "r"(b1));
}

// ---------------- GEMM1: h1(fp16) = x(fp32) @ W1 -----------------------------
__global__ __launch_bounds__(256)
void gemm1_kernel(const float* __restrict__ A,
                  const unsigned* __restrict__ Wp,
                  __half* __restrict__ out, int M) {
    constexpr int K = IN_CH, NC = HID_CH;
    constexpr int STRIDE = 20;
    constexpr int WARPS_M = 4;      // WARPS_N = 2
    constexpr int MT = 2;

    __shared__ unsigned As[128 * STRIDE];
    __shared__ unsigned Bs[NC * STRIDE];

    int tid = threadIdx.x, wid = tid >> 5, lane = tid & 31;
    int g = lane >> 2, t4 = lane & 3;
    int warp_m = (wid % WARPS_M) * (MT * 16);
    int warp_n = (wid / WARPS_M) * 64;
    int m0 = blockIdx.x * 128;

    float acc[MT][8][4];
#pragma unroll
    for (int mt = 0; mt < MT; mt++)
#pragma unroll
        for (int nt = 0; nt < 8; nt++)
#pragma unroll
            for (int i = 0; i < 4; i++) acc[mt][nt][i] = 0.0f;

    for (int kk = 0; kk < K; kk += 32) {
#pragma unroll
        for (int i = 0; i < 4; i++) {
            int idx = i * 256 + tid;
            int r = idx >> 3, c4 = idx & 7;
            int gm = m0 + r;
            uint2 w = make_uint2(0u, 0u);
            if (gm < M) {
                float4 v = *(const float4*)(A + (size_t)gm * K + kk + c4 * 4);
                __half2 p0 = __floats2half2_rn(v.x, v.y);
                __half2 p1 = __floats2half2_rn(v.z, v.w);
                w.x = *reinterpret_cast<unsigned*>(&p0);
                w.y = *reinterpret_cast<unsigned*>(&p1);
            }
            *(uint2*)&As[r * STRIDE + c4 * 2] = w;
        }
        {
            // B chunk: (32/2) * 128 = 2048 packed words -> 8 x 256
            const unsigned* wp = Wp + (size_t)(kk >> 1) * NC;
#pragma unroll
            for (int i = 0; i < 8; i++) {
                int idx = i * 256 + tid;
                int n = idx & 127, k2 = idx >> 7;
                Bs[n * STRIDE + k2] = wp[idx];
            }
        }
        __syncthreads();

#pragma unroll
        for (int ks = 0; ks < 2; ks++) {
            unsigned a[MT][4];
#pragma unroll
            for (int mt = 0; mt < MT; mt++) {
                int r0 = (warp_m + mt * 16 + g) * STRIDE + ks * 8 + t4;
                int r1 = (warp_m + mt * 16 + g + 8) * STRIDE + ks * 8 + t4;
                a[mt][0] = As[r0];     a[mt][1] = As[r1];
                a[mt][2] = As[r0 + 4]; a[mt][3] = As[r1 + 4];
            }
#pragma unroll
            for (int nt = 0; nt < 8; nt++) {
                int bi = (warp_n + nt * 8 + g) * STRIDE + ks * 8 + t4;
                unsigned b0 = Bs[bi], b1 = Bs[bi + 4];
#pragma unroll
                for (int mt = 0; mt < MT; mt++)
                    mma_f16(acc[mt][nt], a[mt], b0, b1);
            }
        }
        __syncthreads();
    }

#pragma unroll
    for (int mt = 0; mt < MT; mt++) {
        int r0 = m0 + warp_m + mt * 16 + g;
        int r1 = r0 + 8;
#pragma unroll
        for (int nt = 0; nt < 8; nt++) {
            int col = warp_n + nt * 8 + t4 * 2;
            if (r0 < M)
                *(__half2*)(out + (size_t)r0 * NC + col) =
                    __floats2half2_rn(acc[mt][nt][0], acc[mt][nt][1]);
            if (r1 < M)
                *(__half2*)(out + (size_t)r1 * NC + col) =
                    __floats2half2_rn(acc[mt][nt][2], acc[mt][nt][3]);
        }
    }
}

// ---------------- 8x fp16 -> 8x fp32 unpack ----------------------------------
__device__ __forceinline__ void h8_acc(uint4 u, float w, float* acc) {
    float2 f0 = __half22float2(*reinterpret_cast<__half2*>(&u.x));
    float2 f1 = __half22float2(*reinterpret_cast<__half2*>(&u.y));
    float2 f2 = __half22float2(*reinterpret_cast<__half2*>(&u.z));
    float2 f3 = __half22float2(*reinterpret_cast<__half2*>(&u.w));
    acc[0] += w * f0.x; acc[1] += w * f0.y;
    acc[2] += w * f1.x; acc[3] += w * f1.y;
    acc[4] += w * f2.x; acc[5] += w * f2.y;
    acc[6] += w * f3.x; acc[7] += w * f3.y;
}

// ---------------- FUSED: agg1 (CSR) + relu + GEMM2 --------------------------
// Phase 1: 16-lane subgroups, uint4 row loads -> 2 nodes per warp in flight.
// Phase 2: mma vs W2 on the smem A-tile (STRIDE-20 fragment layout).
__global__ __launch_bounds__(256)
void agg1_gemm2_kernel(const float* __restrict__ b1,
                       const unsigned* __restrict__ Wp,
                       __half* __restrict__ out, int M) {
    constexpr int STRIDE = 20;
    constexpr int NC = OUT_CH;      // 64

    __shared__ unsigned As[4][128 * STRIDE];   // 4 k-chunks of 32
    __shared__ unsigned Bs[NC * STRIDE];

    int tid = threadIdx.x, wid = tid >> 5, lane = tid & 31;
    int g = lane >> 2, t4 = lane & 3;
    int m0 = blockIdx.x * 128;

    // ---- phase 1: 16 lanes per node, channels 8*hl .. 8*hl+7 ----
    int half = lane >> 4;           // 0/1: which node of the pair
    int hl   = lane & 15;           // lane within subgroup
    float4 bA = ((const float4*)b1)[2 * hl];
    float4 bB = ((const float4*)b1)[2 * hl + 1];
    int chunk = hl >> 2;            // channel block of 32
    int word  = (hl & 3) * 4;       // word offset within chunk row

#pragma unroll 1
    for (int i = 0; i < 8; i++) {
        int r = wid * 16 + i * 2 + half;
        int node = m0 + r;
        uint4 u = make_uint4(0u, 0u, 0u, 0u);
        if (node < M) {
            int beg = g_rowstart[node];
            int cnt = g_cnt[node];
            float acc[8];
#pragma unroll
            for (int k = 0; k < 8; k++) acc[k] = 0.0f;
            int j = 0;
            for (; j + 3 < cnt; j += 4) {
                int2 e0 = __ldg(&g_csr[beg + j]);
                int2 e1 = __ldg(&g_csr[beg + j + 1]);
                int2 e2 = __ldg(&g_csr[beg + j + 2]);
                int2 e3 = __ldg(&g_csr[beg + j + 3]);
                uint4 v0 = __ldg((const uint4*)(g_h1h + (size_t)e0.x * HID_CH) + hl);
                uint4 v1 = __ldg((const uint4*)(g_h1h + (size_t)e1.x * HID_CH) + hl);
                uint4 v2 = __ldg((const uint4*)(g_h1h + (size_t)e2.x * HID_CH) + hl);
                uint4 v3 = __ldg((const uint4*)(g_h1h + (size_t)e3.x * HID_CH) + hl);
                h8_acc(v0, __int_as_float(e0.y), acc);
                h8_acc(v1, __int_as_float(e1.y), acc);
                h8_acc(v2, __int_as_float(e2.y), acc);
                h8_acc(v3, __int_as_float(e3.y), acc);
            }
            for (; j < cnt; j++) {
                int2 e = __ldg(&g_csr[beg + j]);
                uint4 v = __ldg((const uint4*)(g_h1h + (size_t)e.x * HID_CH) + hl);
                h8_acc(v, __int_as_float(e.y), acc);
            }
            float di = g_dinv[node];
            float sw = di * di;
            uint4 hv = *((const uint4*)(g_h1h + (size_t)node * HID_CH) + hl);
            h8_acc(hv, sw, acc);
            acc[0] = fmaxf(acc[0] + bA.x, 0.f);
            acc[1] = fmaxf(acc[1] + bA.y, 0.f);
            acc[2] = fmaxf(acc[2] + bA.z, 0.f);
            acc[3] = fmaxf(acc[3] + bA.w, 0.f);
            acc[4] = fmaxf(acc[4] + bB.x, 0.f);
            acc[5] = fmaxf(acc[5] + bB.y, 0.f);
            acc[6] = fmaxf(acc[6] + bB.z, 0.f);
            acc[7] = fmaxf(acc[7] + bB.w, 0.f);
            __half2 p0 = __floats2half2_rn(acc[0], acc[1]);
            __half2 p1 = __floats2half2_rn(acc[2], acc[3]);
            __half2 p2 = __floats2half2_rn(acc[4], acc[5]);
            __half2 p3 = __floats2half2_rn(acc[6], acc[7]);
            u.x = *reinterpret_cast<unsigned*>(&p0);
            u.y = *reinterpret_cast<unsigned*>(&p1);
            u.z = *reinterpret_cast<unsigned*>(&p2);
            u.w = *reinterpret_cast<unsigned*>(&p3);
        }
        *(uint4*)&As[chunk][r * STRIDE + word] = u;
    }
    __syncthreads();

    // ---- phase 2: GEMM vs W2 (K=128, NC=64; 8 warps over M) ----
    int warp_m = wid * 16;
    float acc[8][4];
#pragma unroll
    for (int nt = 0; nt < 8; nt++)
#pragma unroll
        for (int i = 0; i < 4; i++) acc[nt][i] = 0.0f;

#pragma unroll
    for (int c = 0; c < 4; c++) {
        {
            // B chunk: (32/2) * 64 = 1024 packed words -> 4 x 256
            const unsigned* wp = Wp + (size_t)(c * 16) * NC;
#pragma unroll
            for (int i = 0; i < 4; i++) {
                int idx = i * 256 + tid;
                int n = idx & 63, k2 = idx >> 6;
                Bs[n * STRIDE + k2] = wp[idx];
            }
        }
        __syncthreads();

#pragma unroll
        for (int ks = 0; ks < 2; ks++) {
            unsigned a[4];
            int r0 = (warp_m + g) * STRIDE + ks * 8 + t4;
            int r1 = (warp_m + g + 8) * STRIDE + ks * 8 + t4;
            a[0] = As[c][r0];     a[1] = As[c][r1];
            a[2] = As[c][r0 + 4]; a[3] = As[c][r1 + 4];
#pragma unroll
            for (int nt = 0; nt < 8; nt++) {
                int bi = (nt * 8 + g) * STRIDE + ks * 8 + t4;
                unsigned b0 = Bs[bi], b1 = Bs[bi + 4];
                mma_f16(acc[nt], a, b0, b1);
            }
        }
        __syncthreads();
    }

    // ---- epilogue: h2 fp16 ----
    int r0 = m0 + warp_m + g;
    int r1 = r0 + 8;
#pragma unroll
    for (int nt = 0; nt < 8; nt++) {
        int col = nt * 8 + t4 * 2;
        if (r0 < M)
            *(__half2*)(out + (size_t)r0 * NC + col) =
                __floats2half2_rn(acc[nt][0], acc[nt][1]);
        if (r1 < M)
            *(__half2*)(out + (size_t)r1 * NC + col) =
                __floats2half2_rn(acc[nt][2], acc[nt][3]);
    }
}

// ---------------- CSR aggregation: layer 2 (8 lanes per node, uint4) --------
__global__ __launch_bounds__(256)
void agg2_kernel(const float* __restrict__ b2, float* __restrict__ out) {
    int t = blockIdx.x * blockDim.x + threadIdx.x;
    int node = t >> 3;
    int l8 = t & 7;                 // channels 8*l8 .. 8*l8+7
    if (node >= N_NODES) return;
    int beg = g_rowstart[node];
    int cnt = g_cnt[node];

    float acc[8];
#pragma unroll
    for (int k = 0; k < 8; k++) acc[k] = 0.0f;
    int j = 0;
    for (; j + 3 < cnt; j += 4) {
        int2 e0 = __ldg(&g_csr[beg + j]);
        int2 e1 = __ldg(&g_csr[beg + j + 1]);
        int2 e2 = __ldg(&g_csr[beg + j + 2]);
        int2 e3 = __ldg(&g_csr[beg + j + 3]);
        uint4 v0 = __ldg((const uint4*)(g_h2h + (size_t)e0.x * OUT_CH) + l8);
        uint4 v1 = __ldg((const uint4*)(g_h2h + (size_t)e1.x * OUT_CH) + l8);
        uint4 v2 = __ldg((const uint4*)(g_h2h + (size_t)e2.x * OUT_CH) + l8);
        uint4 v3 = __ldg((const uint4*)(g_h2h + (size_t)e3.x * OUT_CH) + l8);
        h8_acc(v0, __int_as_float(e0.y), acc);
        h8_acc(v1, __int_as_float(e1.y), acc);
        h8_acc(v2, __int_as_float(e2.y), acc);
        h8_acc(v3, __int_as_float(e3.y), acc);
    }
    for (; j < cnt; j++) {
        int2 e = __ldg(&g_csr[beg + j]);
        uint4 v = __ldg((const uint4*)(g_h2h + (size_t)e.x * OUT_CH) + l8);
        h8_acc(v, __int_as_float(e.y), acc);
    }
    float di = g_dinv[node];
    float sw = di * di;
    uint4 hv = *((const uint4*)(g_h2h + (size_t)node * OUT_CH) + l8);
    h8_acc(hv, sw, acc);
    float4 bA = ((const float4*)b2)[2 * l8];
    float4 bB = ((const float4*)b2)[2 * l8 + 1];
    float4 o0 = make_float4(acc[0] + bA.x, acc[1] + bA.y,
                            acc[2] + bA.z, acc[3] + bA.w);
    float4 o1 = make_float4(acc[4] + bB.x, acc[5] + bB.y,
                            acc[6] + bB.z, acc[7] + bB.w);
    float* dst = out + (size_t)node * OUT_CH + l8 * 8;
    *(float4*)dst = o0;
    *(float4*)(dst + 4) = o1;
}

// ---------------- launch ----------------------------------------------------
extern "C" void kernel_launch(void* const* d_in, const int* in_sizes, int n_in,
                              void* d_out, int out_size) {
    const float* x  = (const float*)d_in[0];
    const void*  ei = d_in[1];
    const float* W1 = (const float*)d_in[2];
    const float* b1 = (const float*)d_in[3];
    const float* W2 = (const float*)d_in[4];
    const float* b2 = (const float*)d_in[5];
    float* out = (float*)d_out;

    __half *p_h1h, *p_h2h;
    unsigned *p_W1p, *p_W2p;
    cudaGetSymbolAddress((void**)&p_h1h, g_h1h);
    cudaGetSymbolAddress((void**)&p_h2h, g_h2h);
    cudaGetSymbolAddress((void**)&p_W1p, g_W1p);
    cudaGetSymbolAddress((void**)&p_W2p, g_W2p);

    static cudaStream_t s_side = nullptr;
    static cudaEvent_t  s_fork = nullptr, s_join = nullptr;
    if (s_side == nullptr) {
        cudaStreamCreateWithFlags(&s_side, cudaStreamNonBlocking);
        cudaEventCreateWithFlags(&s_fork, cudaEventDisableTiming);
        cudaEventCreateWithFlags(&s_join, cudaEventDisableTiming);
    }

    // ---- fork: CSR-build branch concurrent with wpack + GEMM1 ----
    cudaEventRecord(s_fork, 0);
    cudaStreamWaitEvent(s_side, s_fork, 0);

    zero_detect_kernel<<<NB_SCAN, 256, 0, s_side>>>((const unsigned*)ei);
    count_deg_kernel<<<(N_EDGES / 4 + 255) / 256, 256, 0, s_side>>>(ei);
    scan1_kernel<<<NB_SCAN, 256, 0, s_side>>>();
    scan23_kernel<<<NB_SCAN, 256, 0, s_side>>>();
    fill_csr_kernel<<<(N_EDGES / 2 + 255) / 256, 256, 0, s_side>>>(ei);
    cudaEventRecord(s_join, s_side);

    wpack_kernel<<<((IN_CH / 2) * HID_CH + 255) / 256, 256>>>(W1, W2);
    gemm1_kernel<<<(N_NODES + 127) / 128, 256>>>(x, p_W1p, p_h1h, N_NODES);

    cudaStreamWaitEvent(0, s_join, 0);

    // fused agg1 + relu + GEMM2 -> h2
    agg1_gemm2_kernel<<<(N_NODES + 127) / 128, 256>>>(b1, p_W2p, p_h2h, N_NODES);
    // final aggregation -> out
    agg2_kernel<<<(N_NODES * 8 + 255) / 256, 256>>>(b2, out);
}

// round 12
// speedup vs baseline: 3.0930x; 1.0112x over previous
#include <cuda_runtime.h>
#include <cuda_fp16.h>

#define N_NODES 100000
#define N_EDGES 1600000
#define IN_CH   256
#define HID_CH  128
#define OUT_CH  64
#define NB_SCAN ((N_NODES + 255) / 256)   // 391

// ---------------- scratch (device globals; no cudaMalloc allowed) ----------
__device__ int      g_cnt     [N_NODES];
__device__ int      g_rowstart[N_NODES];
__device__ int      g_cursor  [N_NODES];
__device__ int      g_part    [512];
__device__ int2     g_csr     [N_EDGES];          // (src, weight-as-int)
__device__ float    g_dinv    [N_NODES];
__device__ __half   g_h1h[(size_t)N_NODES * HID_CH];   // x @ W1   (fp16)
__device__ __half   g_h2h[(size_t)N_NODES * OUT_CH];   // relu(a1) @ W2 (fp16)
__device__ unsigned g_W1p[(IN_CH / 2) * HID_CH];   // fp16 packed, 2 k per word
__device__ unsigned g_W2p[(HID_CH / 2) * OUT_CH];
__device__ int      g_is64;

// ---------------- prep: zero counters + dtype detect ------------------------
__global__ void zero_detect_kernel(const unsigned* __restrict__ w) {
    int n = blockIdx.x * blockDim.x + threadIdx.x;
    if (n < N_NODES) g_cnt[n] = 0;
    if (n == 0) {
        int is64 = 1;
        for (int i = 0; i < 64; i++)
            if (w[2 * i + 1] != 0u) { is64 = 0; break; }
        g_is64 = is64;
    }
}

// 4 edges per thread
__global__ void count_deg_kernel(const void* __restrict__ ei) {
    int t = blockIdx.x * blockDim.x + threadIdx.x;
    if (t >= N_EDGES / 4) return;
    int d0, d1, d2, d3;
    if (g_is64) {
        const longlong2* p =
            (const longlong2*)((const long long*)ei + N_EDGES);
        longlong2 a = p[2 * t], b = p[2 * t + 1];
        d0 = (int)a.x; d1 = (int)a.y; d2 = (int)b.x; d3 = (int)b.y;
    } else {
        const int4* p = (const int4*)((const int*)ei + N_EDGES);
        int4 a = p[t];
        d0 = a.x; d1 = a.y; d2 = a.z; d3 = a.w;
    }
    atomicAdd(&g_cnt[d0], 1);
    atomicAdd(&g_cnt[d1], 1);
    atomicAdd(&g_cnt[d2], 1);
    atomicAdd(&g_cnt[d3], 1);
}

// ---------------- W pack (fp16, 2 k per word, n-fastest source) -------------
__global__ void wpack_kernel(const float* __restrict__ W1,
                             const float* __restrict__ W2) {
    int i = blockIdx.x * blockDim.x + threadIdx.x;
    if (i < (IN_CH / 2) * HID_CH) {
        int k2 = i / HID_CH, n = i % HID_CH;
        float w0 = W1[(size_t)(2 * k2) * HID_CH + n];
        float w1 = W1[(size_t)(2 * k2 + 1) * HID_CH + n];
        __half2 p = __floats2half2_rn(w0, w1);
        g_W1p[i] = *reinterpret_cast<unsigned*>(&p);
    }
    if (i < (HID_CH / 2) * OUT_CH) {
        int k2 = i / OUT_CH, n = i % OUT_CH;
        float w0 = W2[(size_t)(2 * k2) * OUT_CH + n];
        float w1 = W2[(size_t)(2 * k2 + 1) * OUT_CH + n];
        __half2 p = __floats2half2_rn(w0, w1);
        g_W2p[i] = *reinterpret_cast<unsigned*>(&p);
    }
}

// ---------------- scans (dinv fused into scan1; scan2 fused into scan23) ----
__global__ void scan1_kernel() {
    __shared__ int sm[256];
    int tid = threadIdx.x;
    int i = blockIdx.x * 256 + tid;
    int v = (i < N_NODES) ? g_cnt[i] : 0;
    if (i < N_NODES) g_dinv[i] = rsqrtf((float)(v + 1));   // +1 self-loop
    sm[tid] = v;
    __syncthreads();
#pragma unroll
    for (int off = 1; off < 256; off <<= 1) {
        int t = (tid >= off) ? sm[tid - off] : 0;
        __syncthreads();
        sm[tid] += t;
        __syncthreads();
    }
    if (i < N_NODES) g_rowstart[i] = sm[tid] - v;
    if (tid == 255) g_part[blockIdx.x] = sm[tid];
}

__global__ void scan23_kernel() {
    __shared__ int sm[256];
    int tid = threadIdx.x;
    int v = 0;
    for (int i = tid; i < blockIdx.x; i += 256) v += g_part[i];
    sm[tid] = v;
    __syncthreads();
#pragma unroll
    for (int off = 128; off > 0; off >>= 1) {
        if (tid < off) sm[tid] += sm[tid + off];
        __syncthreads();
    }
    int base = sm[0];
    int i = blockIdx.x * 256 + tid;
    if (i < N_NODES) {
        int r = g_rowstart[i] + base;
        g_rowstart[i] = r;
        g_cursor[i] = r;
    }
}

// ---------------- CSR fill (2 edges per thread) ------------------------------
__global__ void fill_csr_kernel(const void* __restrict__ ei) {
    int t = blockIdx.x * blockDim.x + threadIdx.x;
    if (t >= N_EDGES / 2) return;
    int s0, d0, s1, d1;
    if (g_is64) {
        const longlong2* ps = (const longlong2*)ei;
        const longlong2* pd = (const longlong2*)((const long long*)ei + N_EDGES);
        longlong2 a = ps[t], b = pd[t];
        s0 = (int)a.x; s1 = (int)a.y;
        d0 = (int)b.x; d1 = (int)b.y;
    } else {
        const int2* ps = (const int2*)ei;
        const int2* pd = (const int2*)((const int*)ei + N_EDGES);
        int2 a = ps[t], b = pd[t];
        s0 = a.x; s1 = a.y;
        d0 = b.x; d1 = b.y;
    }
    float w0 = g_dinv[s0] * g_dinv[d0];
    float w1 = g_dinv[s1] * g_dinv[d1];
    int slot0 = atomicAdd(&g_cursor[d0], 1);
    g_csr[slot0] = make_int2(s0, __float_as_int(w0));
    int slot1 = atomicAdd(&g_cursor[d1], 1);
    g_csr[slot1] = make_int2(s1, __float_as_int(w1));
}

// ---------------- tensor-core mma helper -------------------------------------
__device__ __forceinline__ void mma_f16(float* c, const unsigned* a,
                                        unsigned b0, unsigned b1) {
    asm volatile(
        "mma.sync.aligned.m16n8k16.row.col.f32.f16.f16.f32 "
        "{%0,%1,%2,%3},{%4,%5,%6,%7},{%8,%9},{%0,%1,%2,%3};"
        : "+f"(c[0]), "+f"(c[1]), "+f"(c[2]), "+f"(c[3])
        : "r"(a[0]), "r"(a[1]), "r"(a[2]), "r"(a[3]), "r"(b0), "r"(b1));
}

// ---------------- GEMM1: h1(fp16) = x(fp32) @ W1 -----------------------------
__global__ __launch_bounds__(256)
void gemm1_kernel(const float* __restrict__ A,
                  const unsigned* __restrict__ Wp,
                  __half* __restrict__ out, int M) {
    constexpr int K = IN_CH, NC = HID_CH;
    constexpr int STRIDE = 20;
    constexpr int WARPS_M = 4;      // WARPS_N = 2
    constexpr int MT = 2;

    __shared__ unsigned As[128 * STRIDE];
    __shared__ unsigned Bs[NC * STRIDE];

    int tid = threadIdx.x, wid = tid >> 5, lane = tid & 31;
    int g = lane >> 2, t4 = lane & 3;
    int warp_m = (wid % WARPS_M) * (MT * 16);
    int warp_n = (wid / WARPS_M) * 64;
    int m0 = blockIdx.x * 128;

    float acc[MT][8][4];
#pragma unroll
    for (int mt = 0; mt < MT; mt++)
#pragma unroll
        for (int nt = 0; nt < 8; nt++)
#pragma unroll
            for (int i = 0; i < 4; i++) acc[mt][nt][i] = 0.0f;

    for (int kk = 0; kk < K; kk += 32) {
#pragma unroll
        for (int i = 0; i < 4; i++) {
            int idx = i * 256 + tid;
            int r = idx >> 3, c4 = idx & 7;
            int gm = m0 + r;
            uint2 w = make_uint2(0u, 0u);
            if (gm < M) {
                float4 v = *(const float4*)(A + (size_t)gm * K + kk + c4 * 4);
                __half2 p0 = __floats2half2_rn(v.x, v.y);
                __half2 p1 = __floats2half2_rn(v.z, v.w);
                w.x = *reinterpret_cast<unsigned*>(&p0);
                w.y = *reinterpret_cast<unsigned*>(&p1);
            }
            *(uint2*)&As[r * STRIDE + c4 * 2] = w;
        }
        {
            // B chunk: (32/2) * 128 = 2048 packed words -> 8 x 256
            const unsigned* wp = Wp + (size_t)(kk >> 1) * NC;
#pragma unroll
            for (int i = 0; i < 8; i++) {
                int idx = i * 256 + tid;
                int n = idx & 127, k2 = idx >> 7;
                Bs[n * STRIDE + k2] = wp[idx];
            }
        }
        __syncthreads();

#pragma unroll
        for (int ks = 0; ks < 2; ks++) {
            unsigned a[MT][4];
#pragma unroll
            for (int mt = 0; mt < MT; mt++) {
                int r0 = (warp_m + mt * 16 + g) * STRIDE + ks * 8 + t4;
                int r1 = (warp_m + mt * 16 + g + 8) * STRIDE + ks * 8 + t4;
                a[mt][0] = As[r0];     a[mt][1] = As[r1];
                a[mt][2] = As[r0 + 4]; a[mt][3] = As[r1 + 4];
            }
#pragma unroll
            for (int nt = 0; nt < 8; nt++) {
                int bi = (warp_n + nt * 8 + g) * STRIDE + ks * 8 + t4;
                unsigned b0 = Bs[bi], b1 = Bs[bi + 4];
#pragma unroll
                for (int mt = 0; mt < MT; mt++)
                    mma_f16(acc[mt][nt], a[mt], b0, b1);
            }
        }
        __syncthreads();
    }

#pragma unroll
    for (int mt = 0; mt < MT; mt++) {
        int r0 = m0 + warp_m + mt * 16 + g;
        int r1 = r0 + 8;
#pragma unroll
        for (int nt = 0; nt < 8; nt++) {
            int col = warp_n + nt * 8 + t4 * 2;
            if (r0 < M)
                *(__half2*)(out + (size_t)r0 * NC + col) =
                    __floats2half2_rn(acc[mt][nt][0], acc[mt][nt][1]);
            if (r1 < M)
                *(__half2*)(out + (size_t)r1 * NC + col) =
                    __floats2half2_rn(acc[mt][nt][2], acc[mt][nt][3]);
        }
    }
}

// ---------------- 8x fp16 -> 8x fp32 unpack ----------------------------------
__device__ __forceinline__ void h8_acc(uint4 u, float w, float* acc) {
    float2 f0 = __half22float2(*reinterpret_cast<__half2*>(&u.x));
    float2 f1 = __half22float2(*reinterpret_cast<__half2*>(&u.y));
    float2 f2 = __half22float2(*reinterpret_cast<__half2*>(&u.z));
    float2 f3 = __half22float2(*reinterpret_cast<__half2*>(&u.w));
    acc[0] += w * f0.x; acc[1] += w * f0.y;
    acc[2] += w * f1.x; acc[3] += w * f1.y;
    acc[4] += w * f2.x; acc[5] += w * f2.y;
    acc[6] += w * f3.x; acc[7] += w * f3.y;
}

// ---------------- FUSED: agg1 (CSR) + relu + GEMM2 --------------------------
// Phase 1: 16-lane subgroups, uint4 row loads, 8-edge unroll (MLP ~8).
// Phase 2: mma vs W2 on the smem A-tile (STRIDE-20 fragment layout).
__global__ __launch_bounds__(256)
void agg1_gemm2_kernel(const float* __restrict__ b1,
                       const unsigned* __restrict__ Wp,
                       __half* __restrict__ out, int M) {
    constexpr int STRIDE = 20;
    constexpr int NC = OUT_CH;      // 64

    __shared__ unsigned As[4][128 * STRIDE];   // 4 k-chunks of 32
    __shared__ unsigned Bs[NC * STRIDE];

    int tid = threadIdx.x, wid = tid >> 5, lane = tid & 31;
    int g = lane >> 2, t4 = lane & 3;
    int m0 = blockIdx.x * 128;

    // ---- phase 1: 16 lanes per node, channels 8*hl .. 8*hl+7 ----
    int half = lane >> 4;           // 0/1: which node of the pair
    int hl   = lane & 15;           // lane within subgroup
    float4 bA = ((const float4*)b1)[2 * hl];
    float4 bB = ((const float4*)b1)[2 * hl + 1];
    int chunk = hl >> 2;            // channel block of 32
    int word  = (hl & 3) * 4;       // word offset within chunk row

#pragma unroll 1
    for (int i = 0; i < 8; i++) {
        int r = wid * 16 + i * 2 + half;
        int node = m0 + r;
        uint4 u = make_uint4(0u, 0u, 0u, 0u);
        if (node < M) {
            int beg = g_rowstart[node];
            int cnt = g_cnt[node];
            float acc[8];
#pragma unroll
            for (int k = 0; k < 8; k++) acc[k] = 0.0f;
            int j = 0;
            for (; j + 7 < cnt; j += 8) {
                int2 e[8];
                uint4 v[8];
#pragma unroll
                for (int q = 0; q < 8; q++)
                    e[q] = __ldg(&g_csr[beg + j + q]);
#pragma unroll
                for (int q = 0; q < 8; q++)
                    v[q] = __ldg((const uint4*)(g_h1h + (size_t)e[q].x * HID_CH) + hl);
#pragma unroll
                for (int q = 0; q < 8; q++)
                    h8_acc(v[q], __int_as_float(e[q].y), acc);
            }
            for (; j + 3 < cnt; j += 4) {
                int2 e0 = __ldg(&g_csr[beg + j]);
                int2 e1 = __ldg(&g_csr[beg + j + 1]);
                int2 e2 = __ldg(&g_csr[beg + j + 2]);
                int2 e3 = __ldg(&g_csr[beg + j + 3]);
                uint4 v0 = __ldg((const uint4*)(g_h1h + (size_t)e0.x * HID_CH) + hl);
                uint4 v1 = __ldg((const uint4*)(g_h1h + (size_t)e1.x * HID_CH) + hl);
                uint4 v2 = __ldg((const uint4*)(g_h1h + (size_t)e2.x * HID_CH) + hl);
                uint4 v3 = __ldg((const uint4*)(g_h1h + (size_t)e3.x * HID_CH) + hl);
                h8_acc(v0, __int_as_float(e0.y), acc);
                h8_acc(v1, __int_as_float(e1.y), acc);
                h8_acc(v2, __int_as_float(e2.y), acc);
                h8_acc(v3, __int_as_float(e3.y), acc);
            }
            for (; j < cnt; j++) {
                int2 e = __ldg(&g_csr[beg + j]);
                uint4 v = __ldg((const uint4*)(g_h1h + (size_t)e.x * HID_CH) + hl);
                h8_acc(v, __int_as_float(e.y), acc);
            }
            float di = g_dinv[node];
            float sw = di * di;
            uint4 hv = *((const uint4*)(g_h1h + (size_t)node * HID_CH) + hl);
            h8_acc(hv, sw, acc);
            acc[0] = fmaxf(acc[0] + bA.x, 0.f);
            acc[1] = fmaxf(acc[1] + bA.y, 0.f);
            acc[2] = fmaxf(acc[2] + bA.z, 0.f);
            acc[3] = fmaxf(acc[3] + bA.w, 0.f);
            acc[4] = fmaxf(acc[4] + bB.x, 0.f);
            acc[5] = fmaxf(acc[5] + bB.y, 0.f);
            acc[6] = fmaxf(acc[6] + bB.z, 0.f);
            acc[7] = fmaxf(acc[7] + bB.w, 0.f);
            __half2 p0 = __floats2half2_rn(acc[0], acc[1]);
            __half2 p1 = __floats2half2_rn(acc[2], acc[3]);
            __half2 p2 = __floats2half2_rn(acc[4], acc[5]);
            __half2 p3 = __floats2half2_rn(acc[6], acc[7]);
            u.x = *reinterpret_cast<unsigned*>(&p0);
            u.y = *reinterpret_cast<unsigned*>(&p1);
            u.z = *reinterpret_cast<unsigned*>(&p2);
            u.w = *reinterpret_cast<unsigned*>(&p3);
        }
        *(uint4*)&As[chunk][r * STRIDE + word] = u;
    }
    __syncthreads();

    // ---- phase 2: GEMM vs W2 (K=128, NC=64; 8 warps over M) ----
    int warp_m = wid * 16;
    float acc[8][4];
#pragma unroll
    for (int nt = 0; nt < 8; nt++)
#pragma unroll
        for (int i = 0; i < 4; i++) acc[nt][i] = 0.0f;

#pragma unroll
    for (int c = 0; c < 4; c++) {
        {
            // B chunk: (32/2) * 64 = 1024 packed words -> 4 x 256
            const unsigned* wp = Wp + (size_t)(c * 16) * NC;
#pragma unroll
            for (int i = 0; i < 4; i++) {
                int idx = i * 256 + tid;
                int n = idx & 63, k2 = idx >> 6;
                Bs[n * STRIDE + k2] = wp[idx];
            }
        }
        __syncthreads();

#pragma unroll
        for (int ks = 0; ks < 2; ks++) {
            unsigned a[4];
            int r0 = (warp_m + g) * STRIDE + ks * 8 + t4;
            int r1 = (warp_m + g + 8) * STRIDE + ks * 8 + t4;
            a[0] = As[c][r0];     a[1] = As[c][r1];
            a[2] = As[c][r0 + 4]; a[3] = As[c][r1 + 4];
#pragma unroll
            for (int nt = 0; nt < 8; nt++) {
                int bi = (nt * 8 + g) * STRIDE + ks * 8 + t4;
                unsigned b0 = Bs[bi], b1 = Bs[bi + 4];
                mma_f16(acc[nt], a, b0, b1);
            }
        }
        __syncthreads();
    }

    // ---- epilogue: h2 fp16 ----
    int r0 = m0 + warp_m + g;
    int r1 = r0 + 8;
#pragma unroll
    for (int nt = 0; nt < 8; nt++) {
        int col = nt * 8 + t4 * 2;
        if (r0 < M)
            *(__half2*)(out + (size_t)r0 * NC + col) =
                __floats2half2_rn(acc[nt][0], acc[nt][1]);
        if (r1 < M)
            *(__half2*)(out + (size_t)r1 * NC + col) =
                __floats2half2_rn(acc[nt][2], acc[nt][3]);
    }
}

// ---------------- CSR aggregation: layer 2 (8 lanes/node, 8-edge unroll) ----
__global__ __launch_bounds__(256)
void agg2_kernel(const float* __restrict__ b2, float* __restrict__ out) {
    int t = blockIdx.x * blockDim.x + threadIdx.x;
    int node = t >> 3;
    int l8 = t & 7;                 // channels 8*l8 .. 8*l8+7
    if (node >= N_NODES) return;
    int beg = g_rowstart[node];
    int cnt = g_cnt[node];

    float acc[8];
#pragma unroll
    for (int k = 0; k < 8; k++) acc[k] = 0.0f;
    int j = 0;
    for (; j + 7 < cnt; j += 8) {
        int2 e[8];
        uint4 v[8];
#pragma unroll
        for (int q = 0; q < 8; q++)
            e[q] = __ldg(&g_csr[beg + j + q]);
#pragma unroll
        for (int q = 0; q < 8; q++)
            v[q] = __ldg((const uint4*)(g_h2h + (size_t)e[q].x * OUT_CH) + l8);
#pragma unroll
        for (int q = 0; q < 8; q++)
            h8_acc(v[q], __int_as_float(e[q].y), acc);
    }
    for (; j + 3 < cnt; j += 4) {
        int2 e0 = __ldg(&g_csr[beg + j]);
        int2 e1 = __ldg(&g_csr[beg + j + 1]);
        int2 e2 = __ldg(&g_csr[beg + j + 2]);
        int2 e3 = __ldg(&g_csr[beg + j + 3]);
        uint4 v0 = __ldg((const uint4*)(g_h2h + (size_t)e0.x * OUT_CH) + l8);
        uint4 v1 = __ldg((const uint4*)(g_h2h + (size_t)e1.x * OUT_CH) + l8);
        uint4 v2 = __ldg((const uint4*)(g_h2h + (size_t)e2.x * OUT_CH) + l8);
        uint4 v3 = __ldg((const uint4*)(g_h2h + (size_t)e3.x * OUT_CH) + l8);
        h8_acc(v0, __int_as_float(e0.y), acc);
        h8_acc(v1, __int_as_float(e1.y), acc);
        h8_acc(v2, __int_as_float(e2.y), acc);
        h8_acc(v3, __int_as_float(e3.y), acc);
    }
    for (; j < cnt; j++) {
        int2 e = __ldg(&g_csr[beg + j]);
        uint4 v = __ldg((const uint4*)(g_h2h + (size_t)e.x * OUT_CH) + l8);
        h8_acc(v, __int_as_float(e.y), acc);
    }
    float di = g_dinv[node];
    float sw = di * di;
    uint4 hv = *((const uint4*)(g_h2h + (size_t)node * OUT_CH) + l8);
    h8_acc(hv, sw, acc);
    float4 bA = ((const float4*)b2)[2 * l8];
    float4 bB = ((const float4*)b2)[2 * l8 + 1];
    float4 o0 = make_float4(acc[0] + bA.x, acc[1] + bA.y,
                            acc[2] + bA.z, acc[3] + bA.w);
    float4 o1 = make_float4(acc[4] + bB.x, acc[5] + bB.y,
                            acc[6] + bB.z, acc[7] + bB.w);
    float* dst = out + (size_t)node * OUT_CH + l8 * 8;
    *(float4*)dst = o0;
    *(float4*)(dst + 4) = o1;
}

// ---------------- launch ----------------------------------------------------
extern "C" void kernel_launch(void* const* d_in, const int* in_sizes, int n_in,
                              void* d_out, int out_size) {
    const float* x  = (const float*)d_in[0];
    const void*  ei = d_in[1];
    const float* W1 = (const float*)d_in[2];
    const float* b1 = (const float*)d_in[3];
    const float* W2 = (const float*)d_in[4];
    const float* b2 = (const float*)d_in[5];
    float* out = (float*)d_out;

    __half *p_h1h, *p_h2h;
    unsigned *p_W1p, *p_W2p;
    cudaGetSymbolAddress((void**)&p_h1h, g_h1h);
    cudaGetSymbolAddress((void**)&p_h2h, g_h2h);
    cudaGetSymbolAddress((void**)&p_W1p, g_W1p);
    cudaGetSymbolAddress((void**)&p_W2p, g_W2p);

    static cudaStream_t s_side = nullptr;
    static cudaEvent_t  s_fork = nullptr, s_join = nullptr;
    if (s_side == nullptr) {
        cudaStreamCreateWithFlags(&s_side, cudaStreamNonBlocking);
        cudaEventCreateWithFlags(&s_fork, cudaEventDisableTiming);
        cudaEventCreateWithFlags(&s_join, cudaEventDisableTiming);
    }

    // ---- fork: CSR-build branch concurrent with wpack + GEMM1 ----
    cudaEventRecord(s_fork, 0);
    cudaStreamWaitEvent(s_side, s_fork, 0);

    zero_detect_kernel<<<NB_SCAN, 256, 0, s_side>>>((const unsigned*)ei);
    count_deg_kernel<<<(N_EDGES / 4 + 255) / 256, 256, 0, s_side>>>(ei);
    scan1_kernel<<<NB_SCAN, 256, 0, s_side>>>();
    scan23_kernel<<<NB_SCAN, 256, 0, s_side>>>();
    fill_csr_kernel<<<(N_EDGES / 2 + 255) / 256, 256, 0, s_side>>>(ei);
    cudaEventRecord(s_join, s_side);

    wpack_kernel<<<((IN_CH / 2) * HID_CH + 255) / 256, 256>>>(W1, W2);
    gemm1_kernel<<<(N_NODES + 127) / 128, 256>>>(x, p_W1p, p_h1h, N_NODES);

    cudaStreamWaitEvent(0, s_join, 0);

    // fused agg1 + relu + GEMM2 -> h2
    agg1_gemm2_kernel<<<(N_NODES + 127) / 128, 256>>>(b1, p_W2p, p_h2h, N_NODES);
    // final aggregation -> out
    agg2_kernel<<<(N_NODES * 8 + 255) / 256, 256>>>(b2, out);
}